// round 3
// baseline (speedup 1.0000x reference)
#include <cuda_runtime.h>

// ---------------------------------------------------------------------------
// Problem constants
// ---------------------------------------------------------------------------
namespace {
constexpr int B  = 8;
constexpr int N  = 1024;
constexpr int C  = 768;
constexpr int H  = 12;
constexpr int HD = 64;
constexpr int M  = B * N;          // 8192 rows
constexpr int QKVC = 3 * C;        // 2304
constexpr float SCALE = 0.125f;    // HD^-0.5
constexpr float EPS   = 1e-6f;
constexpr float EPS_N = EPS / (float)N;
}

// ---------------------------------------------------------------------------
// Scratch (device globals: no allocation allowed)
// ---------------------------------------------------------------------------
__device__ float g_q[B * H * N * HD];     // 24 MB
__device__ float g_k[B * H * N * HD];     // 24 MB
__device__ float g_v[B * H * N * HD];     // 24 MB
__device__ float g_ctx[M * C];            // 24 MB
__device__ float g_vsum[B * H * HD];      // per-(b,h) sum_m v[m,:]

// ---------------------------------------------------------------------------
// Kernel 1: QKV GEMM  (out[m, co] = sum_k x[m,k] * w_qkv[co,k]),
// scattered into q/k/v in [B,H,N,HD] layout.
// 128x64 CTA tile, 16-wide K panels, 256 threads, 8x4 per thread.
// LDS:FFMA ratio 1.5 B/FFMA (under the 2.0 co-saturation point).
// ---------------------------------------------------------------------------
__global__ __launch_bounds__(256) void qkv_gemm(const float* __restrict__ x,
                                                const float* __restrict__ w) {
    __shared__ float As[16][128];  // [k][row]  (8 KB)
    __shared__ float Bs[16][64];   // [k][col]  (4 KB)

    const int tid = threadIdx.x;
    const int tx  = tid & 15;          // 16 col groups of 4
    const int ty  = tid >> 4;          // 16 row groups of 8
    const int tile_n = blockIdx.x * 64;    // 0..2304
    const int tile_m = blockIdx.y * 128;   // 0..8192

    // A loader: row = tid&127, two k-quads at kqA, kqA+4 (kqA in {0,8})
    const int lrA = tid & 127;
    const int kqA = (tid >> 7) * 8;
    // B loader: row = tid&63, one k-quad kqB in {0,4,8,12}
    const int lrB = tid & 63;
    const int kqB = (tid >> 6) * 4;

    const float* aptr = x + (size_t)(tile_m + lrA) * C + kqA;
    const float* bptr = w + (size_t)(tile_n + lrB) * C + kqB;

    float acc[8][4] = {};

    for (int k0 = 0; k0 < C; k0 += 16) {
        float4 a0 = *(const float4*)(aptr + k0);
        float4 a1 = *(const float4*)(aptr + k0 + 4);
        float4 b  = *(const float4*)(bptr + k0);
        As[kqA + 0][lrA] = a0.x; As[kqA + 1][lrA] = a0.y;
        As[kqA + 2][lrA] = a0.z; As[kqA + 3][lrA] = a0.w;
        As[kqA + 4][lrA] = a1.x; As[kqA + 5][lrA] = a1.y;
        As[kqA + 6][lrA] = a1.z; As[kqA + 7][lrA] = a1.w;
        Bs[kqB + 0][lrB] = b.x;  Bs[kqB + 1][lrB] = b.y;
        Bs[kqB + 2][lrB] = b.z;  Bs[kqB + 3][lrB] = b.w;
        __syncthreads();
#pragma unroll
        for (int kk = 0; kk < 16; kk++) {
            float4 av0 = *(const float4*)&As[kk][ty * 8];
            float4 av1 = *(const float4*)&As[kk][ty * 8 + 4];
            float4 bv  = *(const float4*)&Bs[kk][tx * 4];
            float ar[8] = {av0.x, av0.y, av0.z, av0.w,
                           av1.x, av1.y, av1.z, av1.w};
            float br[4] = {bv.x, bv.y, bv.z, bv.w};
#pragma unroll
            for (int i = 0; i < 8; i++)
#pragma unroll
                for (int j = 0; j < 4; j++)
                    acc[i][j] += ar[i] * br[j];
        }
        __syncthreads();
    }

    // Scatter. tile_n is a multiple of 64, so all 64 cols share (s, h);
    // d = local col. s = which of q/k/v, h = head.
    const int s  = tile_n / C;
    const int hh = (tile_n - s * C) >> 6;
    float* dst = (s == 0) ? g_q : (s == 1) ? g_k : g_v;
    const int d0 = tx * 4;
#pragma unroll
    for (int i = 0; i < 8; i++) {
        int row = tile_m + ty * 8 + i;
        int bb = row >> 10;
        int nn = row & 1023;
        float* o = dst + (((size_t)bb * H + hh) * N + nn) * HD + d0;
        *(float4*)o = make_float4(acc[i][0], acc[i][1], acc[i][2], acc[i][3]);
    }
}

// ---------------------------------------------------------------------------
// Kernel 2: per-(b,h) V row-sum  (for the eps/N numerator term)
// ---------------------------------------------------------------------------
__global__ __launch_bounds__(256) void vsum_kernel() {
    __shared__ float red[256];
    const int bh   = blockIdx.x;
    const int d    = threadIdx.x & 63;
    const int part = threadIdx.x >> 6;   // 0..3
    const float* vp = g_v + (size_t)bh * N * HD;
    float s = 0.f;
#pragma unroll 8
    for (int m = part; m < N; m += 4) s += vp[(size_t)m * HD + d];
    red[threadIdx.x] = s;
    __syncthreads();
    if (threadIdx.x < 64) {
        g_vsum[bh * HD + threadIdx.x] =
            red[threadIdx.x] + red[64 + threadIdx.x] +
            red[128 + threadIdx.x] + red[192 + threadIdx.x];
    }
}

// ---------------------------------------------------------------------------
// Kernel 3: flash attention with policy-masked softmax.
// Grid: (N/64 query tiles, B*H). 256 threads, 4x4 per thread.
// Softmax stats (m, l, alpha) held in registers; reductions over the 16
// tx-lanes via shfl_xor (stays within a warp: tx = lane bits 0..3).
// Smem: Qt (16K) + K/V union (16K) + P (16K) = 48KB exactly.
// ---------------------------------------------------------------------------
__global__ __launch_bounds__(256) void attn_kernel(const float* __restrict__ policy) {
    __shared__ float Qt[64][64];   // [d][row], pre-scaled by SCALE
    __shared__ float KV[64][64];   // Kt as [d][col], then V as [m][d]
    __shared__ float Sm[64][64];   // P as [row][col]

    const int tid = threadIdx.x;
    const int tx  = tid & 15;
    const int ty  = tid >> 4;
    const int bh  = blockIdx.y;
    const int b   = bh / H;
    const int h   = bh - b * H;
    const int n0  = blockIdx.x * 64;

    const size_t base = (size_t)bh * N * HD;
    const float* __restrict__ qp  = g_q + base;
    const float* __restrict__ kp  = g_k + base;
    const float* __restrict__ vp  = g_v + base;
    const float* __restrict__ pol = policy + (size_t)b * N;

    const int lr = tid >> 2;        // 0..63
    const int lu = tid & 3;         // 0..3

    // Load Q tile transposed + scale
#pragma unroll
    for (int vi = 0; vi < 4; vi++) {
        int d0 = lu * 16 + vi * 4;
        float4 qv = *(const float4*)&qp[(size_t)(n0 + lr) * HD + d0];
        Qt[d0 + 0][lr] = qv.x * SCALE;
        Qt[d0 + 1][lr] = qv.y * SCALE;
        Qt[d0 + 2][lr] = qv.z * SCALE;
        Qt[d0 + 3][lr] = qv.w * SCALE;
    }

    float acc[4][4] = {};
    float m_run[4], l_run[4];
#pragma unroll
    for (int i = 0; i < 4; i++) { m_run[i] = -1e30f; l_run[i] = 0.f; }

    for (int kt = 0; kt < 16; kt++) {
        const int kbase = kt * 64;
        __syncthreads();   // (a) prev PV-mma done reading KV/Sm; Qt ready
        // Load K tile transposed into KV
#pragma unroll
        for (int vi = 0; vi < 4; vi++) {
            int d0 = lu * 16 + vi * 4;
            float4 kv = *(const float4*)&kp[(size_t)(kbase + lr) * HD + d0];
            KV[d0 + 0][lr] = kv.x; KV[d0 + 1][lr] = kv.y;
            KV[d0 + 2][lr] = kv.z; KV[d0 + 3][lr] = kv.w;
        }
        float pv4[4];
#pragma unroll
        for (int j = 0; j < 4; j++) pv4[j] = pol[kbase + tx * 4 + j];
        __syncthreads();   // (b) Kt ready

        // S = Q K^T (scaled)
        float s[4][4] = {};
#pragma unroll
        for (int d = 0; d < 64; d++) {
            float4 av = *(const float4*)&Qt[d][ty * 4];
            float4 bv = *(const float4*)&KV[d][tx * 4];
            float ar[4] = {av.x, av.y, av.z, av.w};
            float br[4] = {bv.x, bv.y, bv.z, bv.w};
#pragma unroll
            for (int i = 0; i < 4; i++)
#pragma unroll
                for (int j = 0; j < 4; j++)
                    s[i][j] += ar[i] * br[j];
        }
        __syncthreads();   // (c) all Kt reads done — KV free for V

        // Online softmax, stats in registers.
#pragma unroll
        for (int i = 0; i < 4; i++) {
            float tmax = fmaxf(fmaxf(s[i][0], s[i][1]), fmaxf(s[i][2], s[i][3]));
#pragma unroll
            for (int off = 1; off < 16; off <<= 1)
                tmax = fmaxf(tmax, __shfl_xor_sync(0xffffffffu, tmax, off));
            float m_new = fmaxf(m_run[i], tmax);
            float alpha = __expf(m_run[i] - m_new);
            m_run[i] = m_new;
            const int nq = n0 + ty * 4 + i;
            float rsum = 0.f;
#pragma unroll
            for (int j = 0; j < 4; j++) {
                int kg = kbase + tx * 4 + j;
                float ap = (kg == nq) ? 1.0f : pv4[j];
                float p = __expf(s[i][j] - m_new) * ap;
                s[i][j] = p;
                rsum += p;
            }
#pragma unroll
            for (int off = 1; off < 16; off <<= 1)
                rsum += __shfl_xor_sync(0xffffffffu, rsum, off);
            l_run[i] = l_run[i] * alpha + rsum;
#pragma unroll
            for (int j = 0; j < 4; j++) acc[i][j] *= alpha;
        }

        // Write P; load V tile (natural [m][d]) into KV
#pragma unroll
        for (int i = 0; i < 4; i++)
            *(float4*)&Sm[ty * 4 + i][tx * 4] =
                make_float4(s[i][0], s[i][1], s[i][2], s[i][3]);
#pragma unroll
        for (int vi = 0; vi < 4; vi++) {
            int d0 = lu * 16 + vi * 4;
            *(float4*)&KV[lr][d0] =
                *(const float4*)&vp[(size_t)(kbase + lr) * HD + d0];
        }
        __syncthreads();   // (d) P and V ready

        // acc += P @ V
#pragma unroll
        for (int mI = 0; mI < 64; mI++) {
            float4 bv = *(const float4*)&KV[mI][tx * 4];
            float br[4] = {bv.x, bv.y, bv.z, bv.w};
#pragma unroll
            for (int i = 0; i < 4; i++) {
                float a = Sm[ty * 4 + i][mI];
#pragma unroll
                for (int j = 0; j < 4; j++) acc[i][j] += a * br[j];
            }
        }
    }

    // Epilogue: out = (acc + (eps/N) * Vsum) / (l + eps), write [B,N,C] ctx.
    const float* vs = g_vsum + bh * HD;
    const int d0 = tx * 4;
    float vsr[4];
#pragma unroll
    for (int j = 0; j < 4; j++) vsr[j] = vs[d0 + j];
#pragma unroll
    for (int i = 0; i < 4; i++) {
        float inv = 1.0f / (l_run[i] + EPS);
        int nn = n0 + ty * 4 + i;
        float* o = g_ctx + ((size_t)b * N + nn) * C + h * HD + d0;
        float4 ov;
        ov.x = (acc[i][0] + EPS_N * vsr[0]) * inv;
        ov.y = (acc[i][1] + EPS_N * vsr[1]) * inv;
        ov.z = (acc[i][2] + EPS_N * vsr[2]) * inv;
        ov.w = (acc[i][3] + EPS_N * vsr[3]) * inv;
        *(float4*)o = ov;
    }
}

// ---------------------------------------------------------------------------
// Kernel 4: output projection  out = ctx @ w_proj^T + b_proj
// 128x64 CTA tile, 8x4 per thread (same scheme as qkv_gemm).
// ---------------------------------------------------------------------------
__global__ __launch_bounds__(256) void proj_gemm(const float* __restrict__ w,
                                                 const float* __restrict__ bias,
                                                 float* __restrict__ out) {
    __shared__ float As[16][128];
    __shared__ float Bs[16][64];

    const int tid = threadIdx.x;
    const int tx  = tid & 15;
    const int ty  = tid >> 4;
    const int tile_n = blockIdx.x * 64;    // 0..768
    const int tile_m = blockIdx.y * 128;   // 0..8192

    const int lrA = tid & 127;
    const int kqA = (tid >> 7) * 8;
    const int lrB = tid & 63;
    const int kqB = (tid >> 6) * 4;

    const float* aptr = g_ctx + (size_t)(tile_m + lrA) * C + kqA;
    const float* bptr = w + (size_t)(tile_n + lrB) * C + kqB;

    float acc[8][4] = {};

    for (int k0 = 0; k0 < C; k0 += 16) {
        float4 a0 = *(const float4*)(aptr + k0);
        float4 a1 = *(const float4*)(aptr + k0 + 4);
        float4 b  = *(const float4*)(bptr + k0);
        As[kqA + 0][lrA] = a0.x; As[kqA + 1][lrA] = a0.y;
        As[kqA + 2][lrA] = a0.z; As[kqA + 3][lrA] = a0.w;
        As[kqA + 4][lrA] = a1.x; As[kqA + 5][lrA] = a1.y;
        As[kqA + 6][lrA] = a1.z; As[kqA + 7][lrA] = a1.w;
        Bs[kqB + 0][lrB] = b.x;  Bs[kqB + 1][lrB] = b.y;
        Bs[kqB + 2][lrB] = b.z;  Bs[kqB + 3][lrB] = b.w;
        __syncthreads();
#pragma unroll
        for (int kk = 0; kk < 16; kk++) {
            float4 av0 = *(const float4*)&As[kk][ty * 8];
            float4 av1 = *(const float4*)&As[kk][ty * 8 + 4];
            float4 bv  = *(const float4*)&Bs[kk][tx * 4];
            float ar[8] = {av0.x, av0.y, av0.z, av0.w,
                           av1.x, av1.y, av1.z, av1.w};
            float br[4] = {bv.x, bv.y, bv.z, bv.w};
#pragma unroll
            for (int i = 0; i < 8; i++)
#pragma unroll
                for (int j = 0; j < 4; j++)
                    acc[i][j] += ar[i] * br[j];
        }
        __syncthreads();
    }

    const int col = tile_n + tx * 4;
    float4 bv4 = *(const float4*)&bias[col];
#pragma unroll
    for (int i = 0; i < 8; i++) {
        int row = tile_m + ty * 8 + i;
        float* o = out + (size_t)row * C + col;
        float4 ov;
        ov.x = acc[i][0] + bv4.x;
        ov.y = acc[i][1] + bv4.y;
        ov.z = acc[i][2] + bv4.z;
        ov.w = acc[i][3] + bv4.w;
        *(float4*)o = ov;
    }
}

// ---------------------------------------------------------------------------
// Launch
// ---------------------------------------------------------------------------
extern "C" void kernel_launch(void* const* d_in, const int* in_sizes, int n_in,
                              void* d_out, int out_size) {
    // Resolve inputs by element count (all distinct) — robust to ordering.
    const float* x = nullptr;
    const float* policy = nullptr;
    const float* w_qkv = nullptr;
    const float* w_proj = nullptr;
    const float* b_proj = nullptr;
    for (int i = 0; i < n_in; i++) {
        switch (in_sizes[i]) {
            case B * N * C:   x      = (const float*)d_in[i]; break; // 6291456
            case B * N:       policy = (const float*)d_in[i]; break; // 8192
            case 3 * C * C:   w_qkv  = (const float*)d_in[i]; break; // 1769472
            case C * C:       w_proj = (const float*)d_in[i]; break; // 589824
            case C:           b_proj = (const float*)d_in[i]; break; // 768
            default: break;
        }
    }
    float* out = (float*)d_out;

    qkv_gemm<<<dim3(QKVC / 64, M / 128), 256>>>(x, w_qkv);
    vsum_kernel<<<dim3(B * H), 256>>>();
    attn_kernel<<<dim3(N / 64, B * H), 256>>>(policy);
    proj_gemm<<<dim3(C / 64, M / 128), 256>>>(w_proj, b_proj, out);
}

// round 6
// speedup vs baseline: 1.6053x; 1.6053x over previous
#include <cuda_runtime.h>
#include <cuda_bf16.h>
#include <cstdint>

// ---------------------------------------------------------------------------
// Problem constants
// ---------------------------------------------------------------------------
namespace {
constexpr int B  = 8;
constexpr int N  = 1024;
constexpr int C  = 768;
constexpr int H  = 12;
constexpr int HD = 64;
constexpr int M  = B * N;          // 8192
constexpr int QKVC = 3 * C;        // 2304
constexpr float SCALE = 0.125f;
constexpr float EPS   = 1e-6f;
constexpr float EPS_N = EPS / (float)N;

// HMMA GEMM tiling (mma.sync m16n8k16 bf16 — arch-agnostic, works on sm_100)
constexpr int CTA_M = 128;
constexpr int CTA_N = 256;
constexpr int KC    = 32;          // K chunk (bf16 elems)
constexpr int KP    = 40;          // padded smem row (elems); 20g mod 32 distinct
constexpr int NCH   = C / KC;      // 24 chunks

constexpr int A_BYTES = CTA_M * KP * 2;   // 10240
constexpr int B_BYTES = CTA_N * KP * 2;   // 20480
constexpr int STAGE   = 2 * A_BYTES + 2 * B_BYTES;  // 61440
constexpr int SMEM_GEMM = 2 * STAGE;                // 122880 (double buffer)
}

// ---------------------------------------------------------------------------
// Scratch (device globals; no allocation allowed)
// ---------------------------------------------------------------------------
__device__ float g_q[B * H * N * HD];
__device__ float g_k[B * H * N * HD];
__device__ float g_v[B * H * N * HD];
__device__ float g_vsum[B * H * HD];
__device__ __nv_bfloat16 g_xhi[M * C],     g_xlo[M * C];
__device__ __nv_bfloat16 g_wqhi[QKVC * C], g_wqlo[QKVC * C];
__device__ __nv_bfloat16 g_wphi[C * C],    g_wplo[C * C];
__device__ __nv_bfloat16 g_chi[M * C],     g_clo[M * C];   // attention ctx

// ---------------------------------------------------------------------------
// Helpers
// ---------------------------------------------------------------------------
__device__ __forceinline__ uint32_t smem_u32_of(const void* p) {
    uint32_t a;
    asm("{ .reg .u64 t; cvta.to.shared.u64 t, %1; cvt.u32.u64 %0, t; }"
        : "=r"(a) : "l"(p));
    return a;
}
__device__ __forceinline__ void cp16(uint32_t dst, const void* src) {
    asm volatile("cp.async.cg.shared.global [%0], [%1], 16;"
                 :: "r"(dst), "l"(src));
}
__device__ __forceinline__ void cp_commit() {
    asm volatile("cp.async.commit_group;");
}
template <int NN>
__device__ __forceinline__ void cp_wait() {
    asm volatile("cp.async.wait_group %0;" :: "n"(NN));
}
__device__ __forceinline__ void mma16816(float* d, const uint32_t* a,
                                         const uint32_t* b) {
    asm volatile(
        "mma.sync.aligned.m16n8k16.row.col.f32.bf16.bf16.f32 "
        "{%0,%1,%2,%3}, {%4,%5,%6,%7}, {%8,%9}, {%0,%1,%2,%3};"
        : "+f"(d[0]), "+f"(d[1]), "+f"(d[2]), "+f"(d[3])
        : "r"(a[0]), "r"(a[1]), "r"(a[2]), "r"(a[3]), "r"(b[0]), "r"(b[1]));
}

// ---------------------------------------------------------------------------
// Kernel: fp32 -> (bf16 hi, bf16 lo) split conversion
// ---------------------------------------------------------------------------
__global__ __launch_bounds__(256) void convert_hilo(const float* __restrict__ src,
                                                    int which, int n) {
    __nv_bfloat16 *hi, *lo;
    if (which == 0)      { hi = g_xhi;  lo = g_xlo;  }
    else if (which == 1) { hi = g_wqhi; lo = g_wqlo; }
    else                 { hi = g_wphi; lo = g_wplo; }
    int i = (blockIdx.x * blockDim.x + threadIdx.x) * 4;
    if (i >= n) return;
    float4 v = *(const float4*)(src + i);
    __nv_bfloat16 h0 = __float2bfloat16(v.x), h1 = __float2bfloat16(v.y);
    __nv_bfloat16 h2 = __float2bfloat16(v.z), h3 = __float2bfloat16(v.w);
    __nv_bfloat16 l0 = __float2bfloat16(v.x - __bfloat162float(h0));
    __nv_bfloat16 l1 = __float2bfloat16(v.y - __bfloat162float(h1));
    __nv_bfloat16 l2 = __float2bfloat16(v.z - __bfloat162float(h2));
    __nv_bfloat16 l3 = __float2bfloat16(v.w - __bfloat162float(h3));
    *(__nv_bfloat162*)(hi + i)     = __halves2bfloat162(h0, h1);
    *(__nv_bfloat162*)(hi + i + 2) = __halves2bfloat162(h2, h3);
    *(__nv_bfloat162*)(lo + i)     = __halves2bfloat162(l0, l1);
    *(__nv_bfloat162*)(lo + i + 2) = __halves2bfloat162(l2, l3);
}

// ---------------------------------------------------------------------------
// HMMA mainloop: acc[4][8][4] += split-bf16( A[128,768] @ B[256,768]^T ) tile.
// A/B pointers at tile origin, row stride C. acc indexed [mt][nt][reg].
// ---------------------------------------------------------------------------
__device__ __forceinline__ void gemm_mainloop(
    char* sm,
    const __nv_bfloat16* __restrict__ a_hi, const __nv_bfloat16* __restrict__ a_lo,
    const __nv_bfloat16* __restrict__ b_hi, const __nv_bfloat16* __restrict__ b_lo,
    float acc[4][8][4])
{
    const int tid  = threadIdx.x;
    const int wid  = tid >> 5, lane = tid & 31;
    const int g    = lane >> 2, t = lane & 3;
    const int wm   = (wid & 1) * 64;     // warp m offset
    const int wn   = (wid >> 1) * 64;    // warp n offset

    const uint32_t su = smem_u32_of(sm);

    // Fill one stage via cp.async (A: 512 16B ops x2, B: 1024 x2).
    auto fill = [&](int stage, int kc) {
        const uint32_t sb = su + stage * STAGE;
        const int k0 = kc * KC;
#pragma unroll
        for (int i = 0; i < 2; i++) {
            int idx = tid + i * 256;            // 0..511
            int row = idx >> 2, seg = idx & 3;  // seg*8 elems
            uint32_t d = sb + (row * KP + seg * 8) * 2;
            const __nv_bfloat16* s0 = a_hi + (size_t)row * C + k0 + seg * 8;
            const __nv_bfloat16* s1 = a_lo + (size_t)row * C + k0 + seg * 8;
            cp16(d, s0);
            cp16(d + A_BYTES, s1);
        }
#pragma unroll
        for (int i = 0; i < 4; i++) {
            int idx = tid + i * 256;            // 0..1023
            int row = idx >> 2, seg = idx & 3;
            uint32_t d = sb + 2 * A_BYTES + (row * KP + seg * 8) * 2;
            const __nv_bfloat16* s0 = b_hi + (size_t)row * C + k0 + seg * 8;
            const __nv_bfloat16* s1 = b_lo + (size_t)row * C + k0 + seg * 8;
            cp16(d, s0);
            cp16(d + B_BYTES, s1);
        }
        cp_commit();
    };

    fill(0, 0);

    for (int kc = 0; kc < NCH; kc++) {
        if (kc + 1 < NCH) {
            fill((kc + 1) & 1, kc + 1);
            cp_wait<1>();
        } else {
            cp_wait<0>();
        }
        __syncthreads();

        const char* st = sm + (kc & 1) * STAGE;
        const __nv_bfloat16* Ah = (const __nv_bfloat16*)st;
        const __nv_bfloat16* Al = (const __nv_bfloat16*)(st + A_BYTES);
        const __nv_bfloat16* Bh = (const __nv_bfloat16*)(st + 2 * A_BYTES);
        const __nv_bfloat16* Bl = (const __nv_bfloat16*)(st + 2 * A_BYTES + B_BYTES);

        const __nv_bfloat16* PA[3] = {Ah, Ah, Al};
        const __nv_bfloat16* PB[3] = {Bh, Bl, Bh};

#pragma unroll
        for (int p = 0; p < 3; p++) {
            const __nv_bfloat16* Ap = PA[p];
            const __nv_bfloat16* Bp = PB[p];
#pragma unroll
            for (int ks = 0; ks < KC / 16; ks++) {
                const int ko = ks * 16;
                uint32_t af[4][4], bf[8][2];
#pragma unroll
                for (int mt = 0; mt < 4; mt++) {
                    const int r0 = wm + mt * 16 + g;
                    af[mt][0] = *(const uint32_t*)&Ap[(r0)     * KP + ko + 2 * t];
                    af[mt][1] = *(const uint32_t*)&Ap[(r0 + 8) * KP + ko + 2 * t];
                    af[mt][2] = *(const uint32_t*)&Ap[(r0)     * KP + ko + 2 * t + 8];
                    af[mt][3] = *(const uint32_t*)&Ap[(r0 + 8) * KP + ko + 2 * t + 8];
                }
#pragma unroll
                for (int nt = 0; nt < 8; nt++) {
                    const int n0 = wn + nt * 8 + g;
                    bf[nt][0] = *(const uint32_t*)&Bp[n0 * KP + ko + 2 * t];
                    bf[nt][1] = *(const uint32_t*)&Bp[n0 * KP + ko + 2 * t + 8];
                }
#pragma unroll
                for (int mt = 0; mt < 4; mt++)
#pragma unroll
                    for (int nt = 0; nt < 8; nt++)
                        mma16816(acc[mt][nt], af[mt], bf[nt]);
            }
        }
        __syncthreads();
    }
}

// ---------------------------------------------------------------------------
// Kernel: QKV GEMM (HMMA); epilogue scatters fp32 into q/k/v [B,H,N,HD].
// Grid (QKVC/256, M/128), 256 threads.
// ---------------------------------------------------------------------------
__global__ __launch_bounds__(256, 1) void qkv_tc() {
    extern __shared__ char sm[];
    const int tid = threadIdx.x, wid = tid >> 5, lane = tid & 31;
    const int g = lane >> 2, t = lane & 3;
    const int tile_n = blockIdx.x * CTA_N;
    const int tile_m = blockIdx.y * CTA_M;

    float acc[4][8][4] = {};
    gemm_mainloop(sm,
                  g_xhi  + (size_t)tile_m * C, g_xlo  + (size_t)tile_m * C,
                  g_wqhi + (size_t)tile_n * C, g_wqlo + (size_t)tile_n * C,
                  acc);

    // tile_n is a multiple of 256; 256 | 768 so whole CTA band is one of q/k/v.
    const int s = tile_n / C;
    float* dst = (s == 0) ? g_q : (s == 1) ? g_k : g_v;
    const int hbase = (tile_n - s * C) >> 6;      // first head in band
    const int wm = (wid & 1) * 64, wn = (wid >> 1) * 64;

#pragma unroll
    for (int mt = 0; mt < 4; mt++) {
        const int r0 = tile_m + wm + mt * 16 + g;
#pragma unroll
        for (int nt = 0; nt < 8; nt++) {
            const int col = wn + nt * 8 + 2 * t;   // 0..255 within band
            const int h   = hbase + (col >> 6);
            const int d   = col & 63;
#pragma unroll
            for (int half = 0; half < 2; half++) {
                const int row = r0 + half * 8;
                const int bb = row >> 10, nn = row & 1023;
                float* o = dst + (((size_t)bb * H + h) * N + nn) * HD + d;
                *(float2*)o = make_float2(acc[mt][nt][half * 2],
                                          acc[mt][nt][half * 2 + 1]);
            }
        }
    }
}

// ---------------------------------------------------------------------------
// Kernel: proj GEMM (HMMA); epilogue adds bias, writes fp32 out [M][C].
// ---------------------------------------------------------------------------
__global__ __launch_bounds__(256, 1) void proj_tc(const float* __restrict__ bias,
                                                  float* __restrict__ out) {
    extern __shared__ char sm[];
    const int tid = threadIdx.x, wid = tid >> 5, lane = tid & 31;
    const int g = lane >> 2, t = lane & 3;
    const int tile_n = blockIdx.x * CTA_N;
    const int tile_m = blockIdx.y * CTA_M;

    float acc[4][8][4] = {};
    gemm_mainloop(sm,
                  g_chi  + (size_t)tile_m * C, g_clo  + (size_t)tile_m * C,
                  g_wphi + (size_t)tile_n * C, g_wplo + (size_t)tile_n * C,
                  acc);

    const int wm = (wid & 1) * 64, wn = (wid >> 1) * 64;
#pragma unroll
    for (int mt = 0; mt < 4; mt++) {
        const int r0 = tile_m + wm + mt * 16 + g;
#pragma unroll
        for (int nt = 0; nt < 8; nt++) {
            const int col = tile_n + wn + nt * 8 + 2 * t;
            const float b0 = bias[col], b1 = bias[col + 1];
#pragma unroll
            for (int half = 0; half < 2; half++) {
                const int row = r0 + half * 8;
                float* o = out + (size_t)row * C + col;
                *(float2*)o = make_float2(acc[mt][nt][half * 2] + b0,
                                          acc[mt][nt][half * 2 + 1] + b1);
            }
        }
    }
}

// ---------------------------------------------------------------------------
// Kernel: per-(b,h) V row-sum
// ---------------------------------------------------------------------------
__global__ __launch_bounds__(256) void vsum_kernel() {
    __shared__ float red[256];
    const int bh   = blockIdx.x;
    const int d    = threadIdx.x & 63;
    const int part = threadIdx.x >> 6;
    const float* vp = g_v + (size_t)bh * N * HD;
    float s = 0.f;
#pragma unroll 8
    for (int m = part; m < N; m += 4) s += vp[(size_t)m * HD + d];
    red[threadIdx.x] = s;
    __syncthreads();
    if (threadIdx.x < 64) {
        g_vsum[bh * HD + threadIdx.x] =
            red[threadIdx.x] + red[64 + threadIdx.x] +
            red[128 + threadIdx.x] + red[192 + threadIdx.x];
    }
}

// ---------------------------------------------------------------------------
// Kernel: flash attention with policy-masked softmax (SIMT core).
// Epilogue emits ctx as bf16 hi/lo for the HMMA proj GEMM.
// ---------------------------------------------------------------------------
__global__ __launch_bounds__(256) void attn_kernel(const float* __restrict__ policy) {
    __shared__ float Qt[64][64];
    __shared__ float KV[64][64];
    __shared__ float Sm[64][64];

    const int tid = threadIdx.x;
    const int tx  = tid & 15;
    const int ty  = tid >> 4;
    const int bh  = blockIdx.y;
    const int b   = bh / H;
    const int h   = bh - b * H;
    const int n0  = blockIdx.x * 64;

    const size_t base = (size_t)bh * N * HD;
    const float* __restrict__ qp  = g_q + base;
    const float* __restrict__ kp  = g_k + base;
    const float* __restrict__ vp  = g_v + base;
    const float* __restrict__ pol = policy + (size_t)b * N;

    const int lr = tid >> 2;
    const int lu = tid & 3;

#pragma unroll
    for (int vi = 0; vi < 4; vi++) {
        int d0 = lu * 16 + vi * 4;
        float4 qv = *(const float4*)&qp[(size_t)(n0 + lr) * HD + d0];
        Qt[d0 + 0][lr] = qv.x * SCALE;
        Qt[d0 + 1][lr] = qv.y * SCALE;
        Qt[d0 + 2][lr] = qv.z * SCALE;
        Qt[d0 + 3][lr] = qv.w * SCALE;
    }

    float acc[4][4] = {};
    float m_run[4], l_run[4];
#pragma unroll
    for (int i = 0; i < 4; i++) { m_run[i] = -1e30f; l_run[i] = 0.f; }

    for (int kt = 0; kt < 16; kt++) {
        const int kbase = kt * 64;
        __syncthreads();
#pragma unroll
        for (int vi = 0; vi < 4; vi++) {
            int d0 = lu * 16 + vi * 4;
            float4 kv = *(const float4*)&kp[(size_t)(kbase + lr) * HD + d0];
            KV[d0 + 0][lr] = kv.x; KV[d0 + 1][lr] = kv.y;
            KV[d0 + 2][lr] = kv.z; KV[d0 + 3][lr] = kv.w;
        }
        float pv4[4];
#pragma unroll
        for (int j = 0; j < 4; j++) pv4[j] = pol[kbase + tx * 4 + j];
        __syncthreads();

        float s[4][4] = {};
#pragma unroll
        for (int d = 0; d < 64; d++) {
            float4 av = *(const float4*)&Qt[d][ty * 4];
            float4 bv = *(const float4*)&KV[d][tx * 4];
            float ar[4] = {av.x, av.y, av.z, av.w};
            float br[4] = {bv.x, bv.y, bv.z, bv.w};
#pragma unroll
            for (int i = 0; i < 4; i++)
#pragma unroll
                for (int j = 0; j < 4; j++)
                    s[i][j] += ar[i] * br[j];
        }
        __syncthreads();

#pragma unroll
        for (int i = 0; i < 4; i++) {
            float tmax = fmaxf(fmaxf(s[i][0], s[i][1]), fmaxf(s[i][2], s[i][3]));
#pragma unroll
            for (int off = 1; off < 16; off <<= 1)
                tmax = fmaxf(tmax, __shfl_xor_sync(0xffffffffu, tmax, off));
            float m_new = fmaxf(m_run[i], tmax);
            float alpha = __expf(m_run[i] - m_new);
            m_run[i] = m_new;
            const int nq = n0 + ty * 4 + i;
            float rsum = 0.f;
#pragma unroll
            for (int j = 0; j < 4; j++) {
                int kg = kbase + tx * 4 + j;
                float ap = (kg == nq) ? 1.0f : pv4[j];
                float p = __expf(s[i][j] - m_new) * ap;
                s[i][j] = p;
                rsum += p;
            }
#pragma unroll
            for (int off = 1; off < 16; off <<= 1)
                rsum += __shfl_xor_sync(0xffffffffu, rsum, off);
            l_run[i] = l_run[i] * alpha + rsum;
#pragma unroll
            for (int j = 0; j < 4; j++) acc[i][j] *= alpha;
        }

#pragma unroll
        for (int i = 0; i < 4; i++)
            *(float4*)&Sm[ty * 4 + i][tx * 4] =
                make_float4(s[i][0], s[i][1], s[i][2], s[i][3]);
#pragma unroll
        for (int vi = 0; vi < 4; vi++) {
            int d0 = lu * 16 + vi * 4;
            *(float4*)&KV[lr][d0] =
                *(const float4*)&vp[(size_t)(kbase + lr) * HD + d0];
        }
        __syncthreads();

#pragma unroll
        for (int mI = 0; mI < 64; mI++) {
            float4 bv = *(const float4*)&KV[mI][tx * 4];
            float br[4] = {bv.x, bv.y, bv.z, bv.w};
#pragma unroll
            for (int i = 0; i < 4; i++) {
                float a = Sm[ty * 4 + i][mI];
#pragma unroll
                for (int j = 0; j < 4; j++) acc[i][j] += a * br[j];
            }
        }
    }

    // Epilogue -> ctx as bf16 hi/lo
    const float* vs = g_vsum + bh * HD;
    const int d0 = tx * 4;
    float vsr[4];
#pragma unroll
    for (int j = 0; j < 4; j++) vsr[j] = vs[d0 + j];
#pragma unroll
    for (int i = 0; i < 4; i++) {
        float inv = 1.0f / (l_run[i] + EPS);
        int nn = n0 + ty * 4 + i;
        size_t off = ((size_t)b * N + nn) * C + h * HD + d0;
        float o0 = (acc[i][0] + EPS_N * vsr[0]) * inv;
        float o1 = (acc[i][1] + EPS_N * vsr[1]) * inv;
        float o2 = (acc[i][2] + EPS_N * vsr[2]) * inv;
        float o3 = (acc[i][3] + EPS_N * vsr[3]) * inv;
        __nv_bfloat16 h0 = __float2bfloat16(o0), h1 = __float2bfloat16(o1);
        __nv_bfloat16 h2 = __float2bfloat16(o2), h3 = __float2bfloat16(o3);
        __nv_bfloat16 l0 = __float2bfloat16(o0 - __bfloat162float(h0));
        __nv_bfloat16 l1 = __float2bfloat16(o1 - __bfloat162float(h1));
        __nv_bfloat16 l2 = __float2bfloat16(o2 - __bfloat162float(h2));
        __nv_bfloat16 l3 = __float2bfloat16(o3 - __bfloat162float(h3));
        *(__nv_bfloat162*)(g_chi + off)     = __halves2bfloat162(h0, h1);
        *(__nv_bfloat162*)(g_chi + off + 2) = __halves2bfloat162(h2, h3);
        *(__nv_bfloat162*)(g_clo + off)     = __halves2bfloat162(l0, l1);
        *(__nv_bfloat162*)(g_clo + off + 2) = __halves2bfloat162(l2, l3);
    }
}

// ---------------------------------------------------------------------------
// Launch
// ---------------------------------------------------------------------------
extern "C" void kernel_launch(void* const* d_in, const int* in_sizes, int n_in,
                              void* d_out, int out_size) {
    const float* x = nullptr;
    const float* policy = nullptr;
    const float* w_qkv = nullptr;
    const float* w_proj = nullptr;
    const float* b_proj = nullptr;
    for (int i = 0; i < n_in; i++) {
        switch (in_sizes[i]) {
            case B * N * C:   x      = (const float*)d_in[i]; break;
            case B * N:       policy = (const float*)d_in[i]; break;
            case 3 * C * C:   w_qkv  = (const float*)d_in[i]; break;
            case C * C:       w_proj = (const float*)d_in[i]; break;
            case C:           b_proj = (const float*)d_in[i]; break;
            default: break;
        }
    }
    float* out = (float*)d_out;

    // Unconditional (no static guards). Non-stream API, not captured.
    cudaFuncSetAttribute(qkv_tc,  cudaFuncAttributeMaxDynamicSharedMemorySize, SMEM_GEMM);
    cudaFuncSetAttribute(proj_tc, cudaFuncAttributeMaxDynamicSharedMemorySize, SMEM_GEMM);

    convert_hilo<<<(M * C / 4 + 255) / 256, 256>>>(x, 0, M * C);
    convert_hilo<<<(QKVC * C / 4 + 255) / 256, 256>>>(w_qkv, 1, QKVC * C);
    convert_hilo<<<(C * C / 4 + 255) / 256, 256>>>(w_proj, 2, C * C);

    qkv_tc<<<dim3(QKVC / CTA_N, M / CTA_M), 256, SMEM_GEMM>>>();
    vsum_kernel<<<dim3(B * H), 256>>>();
    attn_kernel<<<dim3(N / 64, B * H), 256>>>(policy);
    proj_tc<<<dim3(C / CTA_N, M / CTA_M), 256, SMEM_GEMM>>>(b_proj, out);
}

// round 7
// speedup vs baseline: 2.6694x; 1.6629x over previous
#include <cuda_runtime.h>
#include <cuda_bf16.h>
#include <cstdint>

// ---------------------------------------------------------------------------
// Problem constants
// ---------------------------------------------------------------------------
namespace {
constexpr int B  = 8;
constexpr int N  = 1024;
constexpr int C  = 768;
constexpr int H  = 12;
constexpr int HD = 64;
constexpr int M  = B * N;          // 8192
constexpr int QKVC = 3 * C;        // 2304
constexpr float SCALE = 0.125f;
constexpr float EPS   = 1e-6f;
constexpr float EPS_N = EPS / (float)N;

// HMMA GEMM tiling (mma.sync m16n8k16 bf16)
constexpr int CTA_M = 128;
constexpr int CTA_N = 256;
constexpr int KC    = 32;
constexpr int KP    = 40;
constexpr int NCH   = C / KC;      // 24

constexpr int A_BYTES = CTA_M * KP * 2;
constexpr int B_BYTES = CTA_N * KP * 2;
constexpr int STAGE   = 2 * A_BYTES + 2 * B_BYTES;
constexpr int SMEM_GEMM = 2 * STAGE;               // 122880

// Attention tiling
constexpr int BQ = 128;            // query tile
constexpr int BK = 64;             // key chunk
constexpr int NKC = N / BK;        // 16
constexpr int QP = 72;             // padded row (elems) for Q/K/Vt smem
// attn smem layout (bytes)
constexpr int AT_TILE  = 64 * QP * 2;              // 9216 (one 64-row operand)
constexpr int AT_QHI   = 0;
constexpr int AT_QLO   = 2 * AT_TILE;              // Q is 128 rows = 2*AT_TILE
constexpr int AT_ST0   = 4 * AT_TILE;              // 36864
constexpr int AT_SSTR  = 4 * AT_TILE;              // stage stride (Khi,Klo,Vthi,Vtlo)
constexpr int AT_POL   = AT_ST0 + 2 * AT_SSTR;     // 110592
constexpr int SMEM_ATTN = AT_POL + N * 4;          // 114688
}

// ---------------------------------------------------------------------------
// Scratch (device globals; no allocation allowed)
// ---------------------------------------------------------------------------
__device__ float g_vsum[B * H * HD];
__device__ __nv_bfloat16 g_xhi[M * C],     g_xlo[M * C];
__device__ __nv_bfloat16 g_wqhi[QKVC * C], g_wqlo[QKVC * C];
__device__ __nv_bfloat16 g_wphi[C * C],    g_wplo[C * C];
__device__ __nv_bfloat16 g_chi[M * C],     g_clo[M * C];     // attention ctx
__device__ __nv_bfloat16 g_qhi[B * H * N * HD], g_qlo[B * H * N * HD]; // [bh][n][d], pre-scaled
__device__ __nv_bfloat16 g_khi[B * H * N * HD], g_klo[B * H * N * HD]; // [bh][n][d]
__device__ __nv_bfloat16 g_vthi[B * H * HD * N], g_vtlo[B * H * HD * N]; // [bh][d][n]

// ---------------------------------------------------------------------------
// Helpers
// ---------------------------------------------------------------------------
__device__ __forceinline__ uint32_t smem_u32_of(const void* p) {
    uint32_t a;
    asm("{ .reg .u64 t; cvta.to.shared.u64 t, %1; cvt.u32.u64 %0, t; }"
        : "=r"(a) : "l"(p));
    return a;
}
__device__ __forceinline__ void cp16(uint32_t dst, const void* src) {
    asm volatile("cp.async.cg.shared.global [%0], [%1], 16;"
                 :: "r"(dst), "l"(src));
}
__device__ __forceinline__ void cp_commit() {
    asm volatile("cp.async.commit_group;");
}
template <int NN>
__device__ __forceinline__ void cp_wait() {
    asm volatile("cp.async.wait_group %0;" :: "n"(NN));
}
__device__ __forceinline__ void mma16816(float* d, const uint32_t* a,
                                         const uint32_t* b) {
    asm volatile(
        "mma.sync.aligned.m16n8k16.row.col.f32.bf16.bf16.f32 "
        "{%0,%1,%2,%3}, {%4,%5,%6,%7}, {%8,%9}, {%0,%1,%2,%3};"
        : "+f"(d[0]), "+f"(d[1]), "+f"(d[2]), "+f"(d[3])
        : "r"(a[0]), "r"(a[1]), "r"(a[2]), "r"(a[3]), "r"(b[0]), "r"(b[1]));
}
// pack two fp32 -> bf16x2 (lo element in low 16 bits)
__device__ __forceinline__ uint32_t pack_bf16x2(float lo, float hi) {
    uint32_t d;
    asm("cvt.rn.bf16x2.f32 %0, %1, %2;" : "=r"(d) : "f"(hi), "f"(lo));
    return d;
}
// split (v0,v1) into packed hi pair + packed residual-lo pair
__device__ __forceinline__ void split2(float v0, float v1,
                                       uint32_t& hi, uint32_t& lo) {
    hi = pack_bf16x2(v0, v1);
    float h0 = __uint_as_float(hi << 16);
    float h1 = __uint_as_float(hi & 0xffff0000u);
    lo = pack_bf16x2(v0 - h0, v1 - h1);
}

// ---------------------------------------------------------------------------
// fp32 -> (bf16 hi, lo) split conversion for x / w_qkv / w_proj
// ---------------------------------------------------------------------------
__global__ __launch_bounds__(256) void convert_hilo(const float* __restrict__ src,
                                                    int which, int n) {
    __nv_bfloat16 *hi, *lo;
    if (which == 0)      { hi = g_xhi;  lo = g_xlo;  }
    else if (which == 1) { hi = g_wqhi; lo = g_wqlo; }
    else                 { hi = g_wphi; lo = g_wplo; }
    int i = (blockIdx.x * blockDim.x + threadIdx.x) * 4;
    if (i >= n) return;
    float4 v = *(const float4*)(src + i);
    uint32_t h01, l01, h23, l23;
    split2(v.x, v.y, h01, l01);
    split2(v.z, v.w, h23, l23);
    *(uint32_t*)(hi + i)     = h01;
    *(uint32_t*)(hi + i + 2) = h23;
    *(uint32_t*)(lo + i)     = l01;
    *(uint32_t*)(lo + i + 2) = l23;
}

// ---------------------------------------------------------------------------
// HMMA mainloop (shared by qkv/proj): acc += split-bf16(A @ B^T) tile
// ---------------------------------------------------------------------------
__device__ __forceinline__ void gemm_mainloop(
    char* sm,
    const __nv_bfloat16* __restrict__ a_hi, const __nv_bfloat16* __restrict__ a_lo,
    const __nv_bfloat16* __restrict__ b_hi, const __nv_bfloat16* __restrict__ b_lo,
    float acc[4][8][4])
{
    const int tid  = threadIdx.x;
    const int wid  = tid >> 5, lane = tid & 31;
    const int g    = lane >> 2, t = lane & 3;
    const int wm   = (wid & 1) * 64;
    const int wn   = (wid >> 1) * 64;

    const uint32_t su = smem_u32_of(sm);

    auto fill = [&](int stage, int kc) {
        const uint32_t sb = su + stage * STAGE;
        const int k0 = kc * KC;
#pragma unroll
        for (int i = 0; i < 2; i++) {
            int idx = tid + i * 256;
            int row = idx >> 2, seg = idx & 3;
            uint32_t d = sb + (row * KP + seg * 8) * 2;
            cp16(d, a_hi + (size_t)row * C + k0 + seg * 8);
            cp16(d + A_BYTES, a_lo + (size_t)row * C + k0 + seg * 8);
        }
#pragma unroll
        for (int i = 0; i < 4; i++) {
            int idx = tid + i * 256;
            int row = idx >> 2, seg = idx & 3;
            uint32_t d = sb + 2 * A_BYTES + (row * KP + seg * 8) * 2;
            cp16(d, b_hi + (size_t)row * C + k0 + seg * 8);
            cp16(d + B_BYTES, b_lo + (size_t)row * C + k0 + seg * 8);
        }
        cp_commit();
    };

    fill(0, 0);

    for (int kc = 0; kc < NCH; kc++) {
        if (kc + 1 < NCH) { fill((kc + 1) & 1, kc + 1); cp_wait<1>(); }
        else              { cp_wait<0>(); }
        __syncthreads();

        const char* st = sm + (kc & 1) * STAGE;
        const __nv_bfloat16* Ah = (const __nv_bfloat16*)st;
        const __nv_bfloat16* Al = (const __nv_bfloat16*)(st + A_BYTES);
        const __nv_bfloat16* Bh = (const __nv_bfloat16*)(st + 2 * A_BYTES);
        const __nv_bfloat16* Bl = (const __nv_bfloat16*)(st + 2 * A_BYTES + B_BYTES);

        const __nv_bfloat16* PA[3] = {Ah, Ah, Al};
        const __nv_bfloat16* PB[3] = {Bh, Bl, Bh};

#pragma unroll
        for (int p = 0; p < 3; p++) {
            const __nv_bfloat16* Ap = PA[p];
            const __nv_bfloat16* Bp = PB[p];
#pragma unroll
            for (int ks = 0; ks < KC / 16; ks++) {
                const int ko = ks * 16;
                uint32_t af[4][4], bf[8][2];
#pragma unroll
                for (int mt = 0; mt < 4; mt++) {
                    const int r0 = wm + mt * 16 + g;
                    af[mt][0] = *(const uint32_t*)&Ap[(r0)     * KP + ko + 2 * t];
                    af[mt][1] = *(const uint32_t*)&Ap[(r0 + 8) * KP + ko + 2 * t];
                    af[mt][2] = *(const uint32_t*)&Ap[(r0)     * KP + ko + 2 * t + 8];
                    af[mt][3] = *(const uint32_t*)&Ap[(r0 + 8) * KP + ko + 2 * t + 8];
                }
#pragma unroll
                for (int nt = 0; nt < 8; nt++) {
                    const int n0 = wn + nt * 8 + g;
                    bf[nt][0] = *(const uint32_t*)&Bp[n0 * KP + ko + 2 * t];
                    bf[nt][1] = *(const uint32_t*)&Bp[n0 * KP + ko + 2 * t + 8];
                }
#pragma unroll
                for (int mt = 0; mt < 4; mt++)
#pragma unroll
                    for (int nt = 0; nt < 8; nt++)
                        mma16816(acc[mt][nt], af[mt], bf[nt]);
            }
        }
        __syncthreads();
    }
}

// ---------------------------------------------------------------------------
// QKV GEMM; epilogue writes q (scaled) / k as hi-lo [bh][n][d], v transposed
// hi-lo [bh][d][n].
// ---------------------------------------------------------------------------
__global__ __launch_bounds__(256, 1) void qkv_tc() {
    extern __shared__ char sm[];
    const int tid = threadIdx.x, wid = tid >> 5, lane = tid & 31;
    const int g = lane >> 2, t = lane & 3;
    const int tile_n = blockIdx.x * CTA_N;
    const int tile_m = blockIdx.y * CTA_M;

    float acc[4][8][4] = {};
    gemm_mainloop(sm,
                  g_xhi  + (size_t)tile_m * C, g_xlo  + (size_t)tile_m * C,
                  g_wqhi + (size_t)tile_n * C, g_wqlo + (size_t)tile_n * C,
                  acc);

    const int s_ = tile_n / C;                 // 0:q 1:k 2:v
    const int hbase = (tile_n - s_ * C) >> 6;
    const int wm = (wid & 1) * 64, wn = (wid >> 1) * 64;

#pragma unroll
    for (int mt = 0; mt < 4; mt++) {
        const int r0 = tile_m + wm + mt * 16 + g;
#pragma unroll
        for (int nt = 0; nt < 8; nt++) {
            const int col = wn + nt * 8 + 2 * t;
            const int h   = hbase + (col >> 6);
            const int d   = col & 63;
#pragma unroll
            for (int half = 0; half < 2; half++) {
                const int row = r0 + half * 8;
                const int bb = row >> 10, nn = row & 1023;
                const int bh = bb * H + h;
                float v0 = acc[mt][nt][half * 2];
                float v1 = acc[mt][nt][half * 2 + 1];
                if (s_ == 0) { v0 *= SCALE; v1 *= SCALE; }
                if (s_ == 2) {
                    // transposed store, element-wise
                    __nv_bfloat16 h0 = __float2bfloat16(v0);
                    __nv_bfloat16 h1 = __float2bfloat16(v1);
                    __nv_bfloat16 l0 = __float2bfloat16(v0 - __bfloat162float(h0));
                    __nv_bfloat16 l1 = __float2bfloat16(v1 - __bfloat162float(h1));
                    size_t o0 = ((size_t)bh * HD + d) * N + nn;
                    size_t o1 = ((size_t)bh * HD + d + 1) * N + nn;
                    g_vthi[o0] = h0; g_vthi[o1] = h1;
                    g_vtlo[o0] = l0; g_vtlo[o1] = l1;
                } else {
                    uint32_t hp, lp;
                    split2(v0, v1, hp, lp);
                    size_t o = ((size_t)bh * N + nn) * HD + d;
                    if (s_ == 0) { *(uint32_t*)(g_qhi + o) = hp; *(uint32_t*)(g_qlo + o) = lp; }
                    else         { *(uint32_t*)(g_khi + o) = hp; *(uint32_t*)(g_klo + o) = lp; }
                }
            }
        }
    }
}

// ---------------------------------------------------------------------------
// per-(b,h) V row-sum from transposed hi/lo V
// ---------------------------------------------------------------------------
__global__ __launch_bounds__(256) void vsum_kernel() {
    __shared__ float red[256];
    const int bh = blockIdx.x;
    const int d    = threadIdx.x >> 2;
    const int part = threadIdx.x & 3;
    const __nv_bfloat16* ph = g_vthi + ((size_t)bh * HD + d) * N + part * 256;
    const __nv_bfloat16* pl = g_vtlo + ((size_t)bh * HD + d) * N + part * 256;
    float s = 0.f;
#pragma unroll 4
    for (int j = 0; j < 128; j++) {
        __nv_bfloat162 a = *(const __nv_bfloat162*)(ph + 2 * j);
        __nv_bfloat162 b = *(const __nv_bfloat162*)(pl + 2 * j);
        s += __bfloat162float(a.x) + __bfloat162float(a.y) +
             __bfloat162float(b.x) + __bfloat162float(b.y);
    }
    red[threadIdx.x] = s;
    __syncthreads();
    if (part == 0)
        g_vsum[bh * HD + d] = red[threadIdx.x] + red[threadIdx.x + 1] +
                              red[threadIdx.x + 2] + red[threadIdx.x + 3];
}

// ---------------------------------------------------------------------------
// HMMA flash attention with policy-masked softmax.
// Grid (N/128, B*H), 256 threads (8 warps x 16 query rows).
// ---------------------------------------------------------------------------
__global__ __launch_bounds__(256, 1) void attn_tc(const float* __restrict__ policy) {
    extern __shared__ char sm[];
    const uint32_t su = smem_u32_of(sm);
    const int tid = threadIdx.x, wid = tid >> 5, lane = tid & 31;
    const int g = lane >> 2, t = lane & 3;
    const int bh = blockIdx.y;
    const int b  = bh / H, h = bh - b * H;
    const int n0 = blockIdx.x * BQ;
    const int wm = wid * 16;

    const __nv_bfloat16* qh = g_qhi + (size_t)bh * N * HD;
    const __nv_bfloat16* ql = g_qlo + (size_t)bh * N * HD;
    const __nv_bfloat16* kh = g_khi + (size_t)bh * N * HD;
    const __nv_bfloat16* kl = g_klo + (size_t)bh * N * HD;
    const __nv_bfloat16* vh = g_vthi + (size_t)bh * HD * N;
    const __nv_bfloat16* vl = g_vtlo + (size_t)bh * HD * N;

    // ---- prologue fills: Q (128x64 hi/lo), policy, KV stage 0 ----
#pragma unroll
    for (int i = 0; i < 4; i++) {
        int idx = tid + i * 256;             // 0..1023
        int row = idx >> 3, seg = idx & 7;
        uint32_t d = su + AT_QHI + (row * QP + seg * 8) * 2;
        cp16(d, qh + ((size_t)(n0 + row)) * HD + seg * 8);
        cp16(d + AT_QLO, ql + ((size_t)(n0 + row)) * HD + seg * 8);
    }
    cp16(su + AT_POL + tid * 16, policy + (size_t)b * N + tid * 4);

    auto fillKV = [&](int stage, int kc) {
        const uint32_t sb = su + AT_ST0 + stage * AT_SSTR;
        const int kbase = kc * BK;
#pragma unroll
        for (int i = 0; i < 2; i++) {
            int idx = tid + i * 256;         // 0..511
            int row = idx >> 3, seg = idx & 7;
            uint32_t off = (row * QP + seg * 8) * 2;
            cp16(sb + off,               kh + ((size_t)(kbase + row)) * HD + seg * 8);
            cp16(sb + AT_TILE + off,     kl + ((size_t)(kbase + row)) * HD + seg * 8);
            cp16(sb + 2 * AT_TILE + off, vh + (size_t)row * N + kbase + seg * 8);
            cp16(sb + 3 * AT_TILE + off, vl + (size_t)row * N + kbase + seg * 8);
        }
        cp_commit();
    };
    fillKV(0, 0);

    const float* pol = (const float*)(sm + AT_POL);
    const __nv_bfloat16* Qh = (const __nv_bfloat16*)(sm + AT_QHI);
    const __nv_bfloat16* Ql = (const __nv_bfloat16*)(sm + AT_QLO);

    float oacc[8][4] = {};
    float m0 = -1e30f, m1 = -1e30f, l0 = 0.f, l1 = 0.f;
    const int qr0 = n0 + wm + g, qr1 = qr0 + 8;

    for (int kc = 0; kc < NKC; kc++) {
        if (kc + 1 < NKC) { fillKV((kc + 1) & 1, kc + 1); cp_wait<1>(); }
        else              { cp_wait<0>(); }
        __syncthreads();

        const char* st = sm + AT_ST0 + (kc & 1) * AT_SSTR;
        const __nv_bfloat16* Kh = (const __nv_bfloat16*)st;
        const __nv_bfloat16* Kl = (const __nv_bfloat16*)(st + AT_TILE);
        const __nv_bfloat16* Vh = (const __nv_bfloat16*)(st + 2 * AT_TILE);
        const __nv_bfloat16* Vl = (const __nv_bfloat16*)(st + 3 * AT_TILE);
        const int kbase = kc * BK;

        // ---- S = Q K^T (split, 3 products) ----
        float s[8][4] = {};
        const __nv_bfloat16* PA[3] = {Qh, Qh, Ql};
        const __nv_bfloat16* PB[3] = {Kh, Kl, Kh};
#pragma unroll
        for (int p = 0; p < 3; p++) {
            const __nv_bfloat16* Ap = PA[p];
            const __nv_bfloat16* Bp = PB[p];
#pragma unroll
            for (int ks = 0; ks < 4; ks++) {
                const int ko = ks * 16;
                uint32_t af[4];
                const int r0 = wm + g;
                af[0] = *(const uint32_t*)&Ap[(r0)     * QP + ko + 2 * t];
                af[1] = *(const uint32_t*)&Ap[(r0 + 8) * QP + ko + 2 * t];
                af[2] = *(const uint32_t*)&Ap[(r0)     * QP + ko + 2 * t + 8];
                af[3] = *(const uint32_t*)&Ap[(r0 + 8) * QP + ko + 2 * t + 8];
#pragma unroll
                for (int nt = 0; nt < 8; nt++) {
                    uint32_t bf[2];
                    bf[0] = *(const uint32_t*)&Bp[(nt * 8 + g) * QP + ko + 2 * t];
                    bf[1] = *(const uint32_t*)&Bp[(nt * 8 + g) * QP + ko + 2 * t + 8];
                    mma16816(s[nt], af, bf);
                }
            }
        }

        // ---- online softmax (max over ALL cols, mask after exp) ----
        float mx0 = -1e30f, mx1 = -1e30f;
#pragma unroll
        for (int nt = 0; nt < 8; nt++) {
            mx0 = fmaxf(mx0, fmaxf(s[nt][0], s[nt][1]));
            mx1 = fmaxf(mx1, fmaxf(s[nt][2], s[nt][3]));
        }
        mx0 = fmaxf(mx0, __shfl_xor_sync(0xffffffffu, mx0, 1));
        mx0 = fmaxf(mx0, __shfl_xor_sync(0xffffffffu, mx0, 2));
        mx1 = fmaxf(mx1, __shfl_xor_sync(0xffffffffu, mx1, 1));
        mx1 = fmaxf(mx1, __shfl_xor_sync(0xffffffffu, mx1, 2));
        const float mn0 = fmaxf(m0, mx0), mn1 = fmaxf(m1, mx1);
        const float a0 = __expf(m0 - mn0), a1 = __expf(m1 - mn1);
        m0 = mn0; m1 = mn1;
        l0 *= a0; l1 *= a1;
#pragma unroll
        for (int nd = 0; nd < 8; nd++) {
            oacc[nd][0] *= a0; oacc[nd][1] *= a0;
            oacc[nd][2] *= a1; oacc[nd][3] *= a1;
        }
        float rs0 = 0.f, rs1 = 0.f;
#pragma unroll
        for (int nt = 0; nt < 8; nt++) {
            const int c0 = kbase + nt * 8 + 2 * t;
            const float ap0 = pol[c0], ap1 = pol[c0 + 1];
            float p00 = __expf(s[nt][0] - m0) * ((c0     == qr0) ? 1.f : ap0);
            float p01 = __expf(s[nt][1] - m0) * ((c0 + 1 == qr0) ? 1.f : ap1);
            float p10 = __expf(s[nt][2] - m1) * ((c0     == qr1) ? 1.f : ap0);
            float p11 = __expf(s[nt][3] - m1) * ((c0 + 1 == qr1) ? 1.f : ap1);
            s[nt][0] = p00; s[nt][1] = p01; s[nt][2] = p10; s[nt][3] = p11;
            rs0 += p00 + p01; rs1 += p10 + p11;
        }
        rs0 += __shfl_xor_sync(0xffffffffu, rs0, 1);
        rs0 += __shfl_xor_sync(0xffffffffu, rs0, 2);
        rs1 += __shfl_xor_sync(0xffffffffu, rs1, 1);
        rs1 += __shfl_xor_sync(0xffffffffu, rs1, 2);
        l0 += rs0; l1 += rs1;

        // ---- O += P V (P in registers, split) ----
#pragma unroll
        for (int kk = 0; kk < 4; kk++) {
            uint32_t ah[4], al[4];
            split2(s[2 * kk][0],     s[2 * kk][1],     ah[0], al[0]);
            split2(s[2 * kk][2],     s[2 * kk][3],     ah[1], al[1]);
            split2(s[2 * kk + 1][0], s[2 * kk + 1][1], ah[2], al[2]);
            split2(s[2 * kk + 1][2], s[2 * kk + 1][3], ah[3], al[3]);
            const int ko = kk * 16;
#pragma unroll
            for (int nd = 0; nd < 8; nd++) {
                uint32_t bh_[2], bl_[2];
                bh_[0] = *(const uint32_t*)&Vh[(nd * 8 + g) * QP + ko + 2 * t];
                bh_[1] = *(const uint32_t*)&Vh[(nd * 8 + g) * QP + ko + 2 * t + 8];
                bl_[0] = *(const uint32_t*)&Vl[(nd * 8 + g) * QP + ko + 2 * t];
                bl_[1] = *(const uint32_t*)&Vl[(nd * 8 + g) * QP + ko + 2 * t + 8];
                mma16816(oacc[nd], ah, bh_);
                mma16816(oacc[nd], al, bh_);
                mma16816(oacc[nd], ah, bl_);
            }
        }
        __syncthreads();
    }

    // ---- epilogue: normalize + eps term, emit ctx hi/lo ----
    const float inv0 = 1.f / (l0 + EPS), inv1 = 1.f / (l1 + EPS);
#pragma unroll
    for (int nd = 0; nd < 8; nd++) {
        const int d = nd * 8 + 2 * t;
        const float vs0 = g_vsum[bh * HD + d];
        const float vs1 = g_vsum[bh * HD + d + 1];
        float o00 = (oacc[nd][0] + EPS_N * vs0) * inv0;
        float o01 = (oacc[nd][1] + EPS_N * vs1) * inv0;
        float o10 = (oacc[nd][2] + EPS_N * vs0) * inv1;
        float o11 = (oacc[nd][3] + EPS_N * vs1) * inv1;
        uint32_t hp, lp;
        size_t o = ((size_t)b * N + qr0) * C + h * HD + d;
        split2(o00, o01, hp, lp);
        *(uint32_t*)(g_chi + o) = hp; *(uint32_t*)(g_clo + o) = lp;
        o = ((size_t)b * N + qr1) * C + h * HD + d;
        split2(o10, o11, hp, lp);
        *(uint32_t*)(g_chi + o) = hp; *(uint32_t*)(g_clo + o) = lp;
    }
}

// ---------------------------------------------------------------------------
// proj GEMM; epilogue adds bias, writes fp32 out
// ---------------------------------------------------------------------------
__global__ __launch_bounds__(256, 1) void proj_tc(const float* __restrict__ bias,
                                                  float* __restrict__ out) {
    extern __shared__ char sm[];
    const int tid = threadIdx.x, wid = tid >> 5, lane = tid & 31;
    const int g = lane >> 2, t = lane & 3;
    const int tile_n = blockIdx.x * CTA_N;
    const int tile_m = blockIdx.y * CTA_M;

    float acc[4][8][4] = {};
    gemm_mainloop(sm,
                  g_chi  + (size_t)tile_m * C, g_clo  + (size_t)tile_m * C,
                  g_wphi + (size_t)tile_n * C, g_wplo + (size_t)tile_n * C,
                  acc);

    const int wm = (wid & 1) * 64, wn = (wid >> 1) * 64;
#pragma unroll
    for (int mt = 0; mt < 4; mt++) {
        const int r0 = tile_m + wm + mt * 16 + g;
#pragma unroll
        for (int nt = 0; nt < 8; nt++) {
            const int col = tile_n + wn + nt * 8 + 2 * t;
            const float b0 = bias[col], b1 = bias[col + 1];
#pragma unroll
            for (int half = 0; half < 2; half++) {
                const int row = r0 + half * 8;
                float* o = out + (size_t)row * C + col;
                *(float2*)o = make_float2(acc[mt][nt][half * 2] + b0,
                                          acc[mt][nt][half * 2 + 1] + b1);
            }
        }
    }
}

// ---------------------------------------------------------------------------
// Launch
// ---------------------------------------------------------------------------
extern "C" void kernel_launch(void* const* d_in, const int* in_sizes, int n_in,
                              void* d_out, int out_size) {
    const float* x = nullptr;
    const float* policy = nullptr;
    const float* w_qkv = nullptr;
    const float* w_proj = nullptr;
    const float* b_proj = nullptr;
    for (int i = 0; i < n_in; i++) {
        switch (in_sizes[i]) {
            case B * N * C:   x      = (const float*)d_in[i]; break;
            case B * N:       policy = (const float*)d_in[i]; break;
            case 3 * C * C:   w_qkv  = (const float*)d_in[i]; break;
            case C * C:       w_proj = (const float*)d_in[i]; break;
            case C:           b_proj = (const float*)d_in[i]; break;
            default: break;
        }
    }
    float* out = (float*)d_out;

    cudaFuncSetAttribute(qkv_tc,  cudaFuncAttributeMaxDynamicSharedMemorySize, SMEM_GEMM);
    cudaFuncSetAttribute(proj_tc, cudaFuncAttributeMaxDynamicSharedMemorySize, SMEM_GEMM);
    cudaFuncSetAttribute(attn_tc, cudaFuncAttributeMaxDynamicSharedMemorySize, SMEM_ATTN);

    convert_hilo<<<(M * C / 4 + 255) / 256, 256>>>(x, 0, M * C);
    convert_hilo<<<(QKVC * C / 4 + 255) / 256, 256>>>(w_qkv, 1, QKVC * C);
    convert_hilo<<<(C * C / 4 + 255) / 256, 256>>>(w_proj, 2, C * C);

    qkv_tc<<<dim3(QKVC / CTA_N, M / CTA_M), 256, SMEM_GEMM>>>();
    vsum_kernel<<<dim3(B * H), 256>>>();
    attn_tc<<<dim3(N / BQ, B * H), 256, SMEM_ATTN>>>(policy);
    proj_tc<<<dim3(C / CTA_N, M / CTA_M), 256, SMEM_GEMM>>>(b_proj, out);
}

// round 8
// speedup vs baseline: 2.7876x; 1.0443x over previous
#include <cuda_runtime.h>
#include <cuda_bf16.h>
#include <cstdint>

// ---------------------------------------------------------------------------
// Problem constants
// ---------------------------------------------------------------------------
namespace {
constexpr int B  = 8;
constexpr int N  = 1024;
constexpr int C  = 768;
constexpr int H  = 12;
constexpr int HD = 64;
constexpr int M  = B * N;          // 8192
constexpr int QKVC = 3 * C;        // 2304
constexpr float SCALE = 0.125f;
constexpr float EPS   = 1e-6f;
constexpr float EPS_N = EPS / (float)N;

// HMMA GEMM tiling (mma.sync m16n8k16 bf16), 128x128 CTA tile, 2 CTAs/SM
constexpr int CTA_M = 128;
constexpr int CTA_N = 128;
constexpr int KC    = 32;
constexpr int KP    = 40;
constexpr int NCH   = C / KC;      // 24

constexpr int A_BYTES = CTA_M * KP * 2;            // 10240
constexpr int B_BYTES = CTA_N * KP * 2;            // 10240
constexpr int STAGE   = 2 * A_BYTES + 2 * B_BYTES; // 40960
constexpr int SMEM_GEMM = 2 * STAGE;               // 81920 -> 2 CTAs/SM

// Attention tiling (unchanged from verified round-7 kernel)
constexpr int BQ = 128;
constexpr int BK = 64;
constexpr int NKC = N / BK;        // 16
constexpr int QP = 72;
constexpr int AT_TILE  = 64 * QP * 2;              // 9216
constexpr int AT_QHI   = 0;
constexpr int AT_QLO   = 2 * AT_TILE;
constexpr int AT_ST0   = 4 * AT_TILE;
constexpr int AT_SSTR  = 4 * AT_TILE;
constexpr int AT_POL   = AT_ST0 + 2 * AT_SSTR;
constexpr int SMEM_ATTN = AT_POL + N * 4;          // 114688
}

// ---------------------------------------------------------------------------
// Scratch (device globals; no allocation allowed)
// ---------------------------------------------------------------------------
__device__ float g_vsum[B * H * HD];
__device__ __nv_bfloat16 g_xhi[M * C],     g_xlo[M * C];
__device__ __nv_bfloat16 g_wqhi[QKVC * C], g_wqlo[QKVC * C];
__device__ __nv_bfloat16 g_wphi[C * C],    g_wplo[C * C];
__device__ __nv_bfloat16 g_chi[M * C],     g_clo[M * C];
__device__ __nv_bfloat16 g_qhi[B * H * N * HD], g_qlo[B * H * N * HD];
__device__ __nv_bfloat16 g_khi[B * H * N * HD], g_klo[B * H * N * HD];
__device__ __nv_bfloat16 g_vthi[B * H * HD * N], g_vtlo[B * H * HD * N];

// ---------------------------------------------------------------------------
// Helpers
// ---------------------------------------------------------------------------
__device__ __forceinline__ uint32_t smem_u32_of(const void* p) {
    uint32_t a;
    asm("{ .reg .u64 t; cvta.to.shared.u64 t, %1; cvt.u32.u64 %0, t; }"
        : "=r"(a) : "l"(p));
    return a;
}
__device__ __forceinline__ void cp16(uint32_t dst, const void* src) {
    asm volatile("cp.async.cg.shared.global [%0], [%1], 16;"
                 :: "r"(dst), "l"(src));
}
__device__ __forceinline__ void cp_commit() {
    asm volatile("cp.async.commit_group;");
}
template <int NN>
__device__ __forceinline__ void cp_wait() {
    asm volatile("cp.async.wait_group %0;" :: "n"(NN));
}
__device__ __forceinline__ void mma16816(float* d, const uint32_t* a,
                                         const uint32_t* b) {
    asm volatile(
        "mma.sync.aligned.m16n8k16.row.col.f32.bf16.bf16.f32 "
        "{%0,%1,%2,%3}, {%4,%5,%6,%7}, {%8,%9}, {%0,%1,%2,%3};"
        : "+f"(d[0]), "+f"(d[1]), "+f"(d[2]), "+f"(d[3])
        : "r"(a[0]), "r"(a[1]), "r"(a[2]), "r"(a[3]), "r"(b[0]), "r"(b[1]));
}
__device__ __forceinline__ uint32_t pack_bf16x2(float lo, float hi) {
    uint32_t d;
    asm("cvt.rn.bf16x2.f32 %0, %1, %2;" : "=r"(d) : "f"(hi), "f"(lo));
    return d;
}
__device__ __forceinline__ void split2(float v0, float v1,
                                       uint32_t& hi, uint32_t& lo) {
    hi = pack_bf16x2(v0, v1);
    float h0 = __uint_as_float(hi << 16);
    float h1 = __uint_as_float(hi & 0xffff0000u);
    lo = pack_bf16x2(v0 - h0, v1 - h1);
}

// ---------------------------------------------------------------------------
// fp32 -> (bf16 hi, lo) split conversion
// ---------------------------------------------------------------------------
__global__ __launch_bounds__(256) void convert_hilo(const float* __restrict__ src,
                                                    int which, int n) {
    __nv_bfloat16 *hi, *lo;
    if (which == 0)      { hi = g_xhi;  lo = g_xlo;  }
    else if (which == 1) { hi = g_wqhi; lo = g_wqlo; }
    else                 { hi = g_wphi; lo = g_wplo; }
    int i = (blockIdx.x * blockDim.x + threadIdx.x) * 4;
    if (i >= n) return;
    float4 v = *(const float4*)(src + i);
    uint32_t h01, l01, h23, l23;
    split2(v.x, v.y, h01, l01);
    split2(v.z, v.w, h23, l23);
    *(uint32_t*)(hi + i)     = h01;
    *(uint32_t*)(hi + i + 2) = h23;
    *(uint32_t*)(lo + i)     = l01;
    *(uint32_t*)(lo + i + 2) = l23;
}

// ---------------------------------------------------------------------------
// HMMA mainloop (128x128 tile, warp tile 32x64, frag-once 3-product split)
// ---------------------------------------------------------------------------
__device__ __forceinline__ void gemm_mainloop(
    char* sm,
    const __nv_bfloat16* __restrict__ a_hi, const __nv_bfloat16* __restrict__ a_lo,
    const __nv_bfloat16* __restrict__ b_hi, const __nv_bfloat16* __restrict__ b_lo,
    float acc[2][8][4])
{
    const int tid  = threadIdx.x;
    const int wid  = tid >> 5, lane = tid & 31;
    const int g    = lane >> 2, t = lane & 3;
    const int wm   = (wid & 3) * 32;     // 4 row groups
    const int wn   = (wid >> 2) * 64;    // 2 col groups

    const uint32_t su = smem_u32_of(sm);

    auto fill = [&](int stage, int kc) {
        const uint32_t sb = su + stage * STAGE;
        const int k0 = kc * KC;
#pragma unroll
        for (int i = 0; i < 2; i++) {
            int idx = tid + i * 256;            // 0..511
            int row = idx >> 2, seg = idx & 3;
            uint32_t d = sb + (row * KP + seg * 8) * 2;
            cp16(d, a_hi + (size_t)row * C + k0 + seg * 8);
            cp16(d + A_BYTES, a_lo + (size_t)row * C + k0 + seg * 8);
            uint32_t db = sb + 2 * A_BYTES + (row * KP + seg * 8) * 2;
            cp16(db, b_hi + (size_t)row * C + k0 + seg * 8);
            cp16(db + B_BYTES, b_lo + (size_t)row * C + k0 + seg * 8);
        }
        cp_commit();
    };

    fill(0, 0);

    for (int kc = 0; kc < NCH; kc++) {
        if (kc + 1 < NCH) { fill((kc + 1) & 1, kc + 1); cp_wait<1>(); }
        else              { cp_wait<0>(); }
        __syncthreads();

        const char* st = sm + (kc & 1) * STAGE;
        const __nv_bfloat16* Ah = (const __nv_bfloat16*)st;
        const __nv_bfloat16* Al = (const __nv_bfloat16*)(st + A_BYTES);
        const __nv_bfloat16* Bh = (const __nv_bfloat16*)(st + 2 * A_BYTES);
        const __nv_bfloat16* Bl = (const __nv_bfloat16*)(st + 2 * A_BYTES + B_BYTES);

#pragma unroll
        for (int ks = 0; ks < KC / 16; ks++) {
            const int ko = ks * 16;
            uint32_t ah[2][4], al[2][4];
#pragma unroll
            for (int mt = 0; mt < 2; mt++) {
                const int r0 = wm + mt * 16 + g;
                ah[mt][0] = *(const uint32_t*)&Ah[(r0)     * KP + ko + 2 * t];
                ah[mt][1] = *(const uint32_t*)&Ah[(r0 + 8) * KP + ko + 2 * t];
                ah[mt][2] = *(const uint32_t*)&Ah[(r0)     * KP + ko + 2 * t + 8];
                ah[mt][3] = *(const uint32_t*)&Ah[(r0 + 8) * KP + ko + 2 * t + 8];
                al[mt][0] = *(const uint32_t*)&Al[(r0)     * KP + ko + 2 * t];
                al[mt][1] = *(const uint32_t*)&Al[(r0 + 8) * KP + ko + 2 * t];
                al[mt][2] = *(const uint32_t*)&Al[(r0)     * KP + ko + 2 * t + 8];
                al[mt][3] = *(const uint32_t*)&Al[(r0 + 8) * KP + ko + 2 * t + 8];
            }
#pragma unroll
            for (int nt = 0; nt < 8; nt++) {
                const int n0 = wn + nt * 8 + g;
                uint32_t bh_[2], bl_[2];
                bh_[0] = *(const uint32_t*)&Bh[n0 * KP + ko + 2 * t];
                bh_[1] = *(const uint32_t*)&Bh[n0 * KP + ko + 2 * t + 8];
                bl_[0] = *(const uint32_t*)&Bl[n0 * KP + ko + 2 * t];
                bl_[1] = *(const uint32_t*)&Bl[n0 * KP + ko + 2 * t + 8];
#pragma unroll
                for (int mt = 0; mt < 2; mt++) {
                    mma16816(acc[mt][nt], ah[mt], bh_);
                    mma16816(acc[mt][nt], ah[mt], bl_);
                    mma16816(acc[mt][nt], al[mt], bh_);
                }
            }
        }
        __syncthreads();
    }
}

// ---------------------------------------------------------------------------
// QKV GEMM; epilogue writes q (scaled) / k hi-lo [bh][n][d], v transposed.
// Grid (QKVC/128, M/128), 256 threads, 2 CTAs/SM.
// ---------------------------------------------------------------------------
__global__ __launch_bounds__(256, 2) void qkv_tc() {
    extern __shared__ char sm[];
    const int tid = threadIdx.x, wid = tid >> 5, lane = tid & 31;
    const int g = lane >> 2, t = lane & 3;
    const int tile_n = blockIdx.x * CTA_N;
    const int tile_m = blockIdx.y * CTA_M;

    float acc[2][8][4] = {};
    gemm_mainloop(sm,
                  g_xhi  + (size_t)tile_m * C, g_xlo  + (size_t)tile_m * C,
                  g_wqhi + (size_t)tile_n * C, g_wqlo + (size_t)tile_n * C,
                  acc);

    const int s_ = tile_n / C;                 // 0:q 1:k 2:v
    const int hbase = (tile_n - s_ * C) >> 6;
    const int wm = (wid & 3) * 32, wn = (wid >> 2) * 64;

#pragma unroll
    for (int mt = 0; mt < 2; mt++) {
        const int r0 = tile_m + wm + mt * 16 + g;
#pragma unroll
        for (int nt = 0; nt < 8; nt++) {
            const int col = wn + nt * 8 + 2 * t;   // 0..127 in band
            const int h   = hbase + (col >> 6);
            const int d   = col & 63;
#pragma unroll
            for (int half = 0; half < 2; half++) {
                const int row = r0 + half * 8;
                const int bb = row >> 10, nn = row & 1023;
                const int bh = bb * H + h;
                float v0 = acc[mt][nt][half * 2];
                float v1 = acc[mt][nt][half * 2 + 1];
                if (s_ == 0) { v0 *= SCALE; v1 *= SCALE; }
                if (s_ == 2) {
                    __nv_bfloat16 h0 = __float2bfloat16(v0);
                    __nv_bfloat16 h1 = __float2bfloat16(v1);
                    __nv_bfloat16 l0 = __float2bfloat16(v0 - __bfloat162float(h0));
                    __nv_bfloat16 l1 = __float2bfloat16(v1 - __bfloat162float(h1));
                    size_t o0 = ((size_t)bh * HD + d) * N + nn;
                    size_t o1 = ((size_t)bh * HD + d + 1) * N + nn;
                    g_vthi[o0] = h0; g_vthi[o1] = h1;
                    g_vtlo[o0] = l0; g_vtlo[o1] = l1;
                } else {
                    uint32_t hp, lp;
                    split2(v0, v1, hp, lp);
                    size_t o = ((size_t)bh * N + nn) * HD + d;
                    if (s_ == 0) { *(uint32_t*)(g_qhi + o) = hp; *(uint32_t*)(g_qlo + o) = lp; }
                    else         { *(uint32_t*)(g_khi + o) = hp; *(uint32_t*)(g_klo + o) = lp; }
                }
            }
        }
    }
}

// ---------------------------------------------------------------------------
// per-(b,h) V row-sum from transposed hi/lo V
// ---------------------------------------------------------------------------
__global__ __launch_bounds__(256) void vsum_kernel() {
    __shared__ float red[256];
    const int bh = blockIdx.x;
    const int d    = threadIdx.x >> 2;
    const int part = threadIdx.x & 3;
    const __nv_bfloat16* ph = g_vthi + ((size_t)bh * HD + d) * N + part * 256;
    const __nv_bfloat16* pl = g_vtlo + ((size_t)bh * HD + d) * N + part * 256;
    float s = 0.f;
#pragma unroll 4
    for (int j = 0; j < 128; j++) {
        __nv_bfloat162 a = *(const __nv_bfloat162*)(ph + 2 * j);
        __nv_bfloat162 b = *(const __nv_bfloat162*)(pl + 2 * j);
        s += __bfloat162float(a.x) + __bfloat162float(a.y) +
             __bfloat162float(b.x) + __bfloat162float(b.y);
    }
    red[threadIdx.x] = s;
    __syncthreads();
    if (part == 0)
        g_vsum[bh * HD + d] = red[threadIdx.x] + red[threadIdx.x + 1] +
                              red[threadIdx.x + 2] + red[threadIdx.x + 3];
}

// ---------------------------------------------------------------------------
// HMMA flash attention with policy-masked softmax (verified round-7 core).
// ---------------------------------------------------------------------------
__global__ __launch_bounds__(256, 1) void attn_tc(const float* __restrict__ policy) {
    extern __shared__ char sm[];
    const uint32_t su = smem_u32_of(sm);
    const int tid = threadIdx.x, wid = tid >> 5, lane = tid & 31;
    const int g = lane >> 2, t = lane & 3;
    const int bh = blockIdx.y;
    const int b  = bh / H, h = bh - b * H;
    const int n0 = blockIdx.x * BQ;
    const int wm = wid * 16;

    const __nv_bfloat16* qh = g_qhi + (size_t)bh * N * HD;
    const __nv_bfloat16* ql = g_qlo + (size_t)bh * N * HD;
    const __nv_bfloat16* kh = g_khi + (size_t)bh * N * HD;
    const __nv_bfloat16* kl = g_klo + (size_t)bh * N * HD;
    const __nv_bfloat16* vh = g_vthi + (size_t)bh * HD * N;
    const __nv_bfloat16* vl = g_vtlo + (size_t)bh * HD * N;

#pragma unroll
    for (int i = 0; i < 4; i++) {
        int idx = tid + i * 256;
        int row = idx >> 3, seg = idx & 7;
        uint32_t d = su + AT_QHI + (row * QP + seg * 8) * 2;
        cp16(d, qh + ((size_t)(n0 + row)) * HD + seg * 8);
        cp16(d + AT_QLO, ql + ((size_t)(n0 + row)) * HD + seg * 8);
    }
    cp16(su + AT_POL + tid * 16, policy + (size_t)b * N + tid * 4);

    auto fillKV = [&](int stage, int kc) {
        const uint32_t sb = su + AT_ST0 + stage * AT_SSTR;
        const int kbase = kc * BK;
#pragma unroll
        for (int i = 0; i < 2; i++) {
            int idx = tid + i * 256;
            int row = idx >> 3, seg = idx & 7;
            uint32_t off = (row * QP + seg * 8) * 2;
            cp16(sb + off,               kh + ((size_t)(kbase + row)) * HD + seg * 8);
            cp16(sb + AT_TILE + off,     kl + ((size_t)(kbase + row)) * HD + seg * 8);
            cp16(sb + 2 * AT_TILE + off, vh + (size_t)row * N + kbase + seg * 8);
            cp16(sb + 3 * AT_TILE + off, vl + (size_t)row * N + kbase + seg * 8);
        }
        cp_commit();
    };
    fillKV(0, 0);

    const float* pol = (const float*)(sm + AT_POL);
    const __nv_bfloat16* Qh = (const __nv_bfloat16*)(sm + AT_QHI);
    const __nv_bfloat16* Ql = (const __nv_bfloat16*)(sm + AT_QLO);

    float oacc[8][4] = {};
    float m0 = -1e30f, m1 = -1e30f, l0 = 0.f, l1 = 0.f;
    const int qr0 = n0 + wm + g, qr1 = qr0 + 8;

    for (int kc = 0; kc < NKC; kc++) {
        if (kc + 1 < NKC) { fillKV((kc + 1) & 1, kc + 1); cp_wait<1>(); }
        else              { cp_wait<0>(); }
        __syncthreads();

        const char* st = sm + AT_ST0 + (kc & 1) * AT_SSTR;
        const __nv_bfloat16* Kh = (const __nv_bfloat16*)st;
        const __nv_bfloat16* Kl = (const __nv_bfloat16*)(st + AT_TILE);
        const __nv_bfloat16* Vh = (const __nv_bfloat16*)(st + 2 * AT_TILE);
        const __nv_bfloat16* Vl = (const __nv_bfloat16*)(st + 3 * AT_TILE);
        const int kbase = kc * BK;

        float s[8][4] = {};
        const __nv_bfloat16* PA[3] = {Qh, Qh, Ql};
        const __nv_bfloat16* PB[3] = {Kh, Kl, Kh};
#pragma unroll
        for (int p = 0; p < 3; p++) {
            const __nv_bfloat16* Ap = PA[p];
            const __nv_bfloat16* Bp = PB[p];
#pragma unroll
            for (int ks = 0; ks < 4; ks++) {
                const int ko = ks * 16;
                uint32_t af[4];
                const int r0 = wm + g;
                af[0] = *(const uint32_t*)&Ap[(r0)     * QP + ko + 2 * t];
                af[1] = *(const uint32_t*)&Ap[(r0 + 8) * QP + ko + 2 * t];
                af[2] = *(const uint32_t*)&Ap[(r0)     * QP + ko + 2 * t + 8];
                af[3] = *(const uint32_t*)&Ap[(r0 + 8) * QP + ko + 2 * t + 8];
#pragma unroll
                for (int nt = 0; nt < 8; nt++) {
                    uint32_t bf[2];
                    bf[0] = *(const uint32_t*)&Bp[(nt * 8 + g) * QP + ko + 2 * t];
                    bf[1] = *(const uint32_t*)&Bp[(nt * 8 + g) * QP + ko + 2 * t + 8];
                    mma16816(s[nt], af, bf);
                }
            }
        }

        float mx0 = -1e30f, mx1 = -1e30f;
#pragma unroll
        for (int nt = 0; nt < 8; nt++) {
            mx0 = fmaxf(mx0, fmaxf(s[nt][0], s[nt][1]));
            mx1 = fmaxf(mx1, fmaxf(s[nt][2], s[nt][3]));
        }
        mx0 = fmaxf(mx0, __shfl_xor_sync(0xffffffffu, mx0, 1));
        mx0 = fmaxf(mx0, __shfl_xor_sync(0xffffffffu, mx0, 2));
        mx1 = fmaxf(mx1, __shfl_xor_sync(0xffffffffu, mx1, 1));
        mx1 = fmaxf(mx1, __shfl_xor_sync(0xffffffffu, mx1, 2));
        const float mn0 = fmaxf(m0, mx0), mn1 = fmaxf(m1, mx1);
        const float a0 = __expf(m0 - mn0), a1 = __expf(m1 - mn1);
        m0 = mn0; m1 = mn1;
        l0 *= a0; l1 *= a1;
#pragma unroll
        for (int nd = 0; nd < 8; nd++) {
            oacc[nd][0] *= a0; oacc[nd][1] *= a0;
            oacc[nd][2] *= a1; oacc[nd][3] *= a1;
        }
        float rs0 = 0.f, rs1 = 0.f;
#pragma unroll
        for (int nt = 0; nt < 8; nt++) {
            const int c0 = kbase + nt * 8 + 2 * t;
            const float ap0 = pol[c0], ap1 = pol[c0 + 1];
            float p00 = __expf(s[nt][0] - m0) * ((c0     == qr0) ? 1.f : ap0);
            float p01 = __expf(s[nt][1] - m0) * ((c0 + 1 == qr0) ? 1.f : ap1);
            float p10 = __expf(s[nt][2] - m1) * ((c0     == qr1) ? 1.f : ap0);
            float p11 = __expf(s[nt][3] - m1) * ((c0 + 1 == qr1) ? 1.f : ap1);
            s[nt][0] = p00; s[nt][1] = p01; s[nt][2] = p10; s[nt][3] = p11;
            rs0 += p00 + p01; rs1 += p10 + p11;
        }
        rs0 += __shfl_xor_sync(0xffffffffu, rs0, 1);
        rs0 += __shfl_xor_sync(0xffffffffu, rs0, 2);
        rs1 += __shfl_xor_sync(0xffffffffu, rs1, 1);
        rs1 += __shfl_xor_sync(0xffffffffu, rs1, 2);
        l0 += rs0; l1 += rs1;

#pragma unroll
        for (int kk = 0; kk < 4; kk++) {
            uint32_t ah[4], al[4];
            split2(s[2 * kk][0],     s[2 * kk][1],     ah[0], al[0]);
            split2(s[2 * kk][2],     s[2 * kk][3],     ah[1], al[1]);
            split2(s[2 * kk + 1][0], s[2 * kk + 1][1], ah[2], al[2]);
            split2(s[2 * kk + 1][2], s[2 * kk + 1][3], ah[3], al[3]);
            const int ko = kk * 16;
#pragma unroll
            for (int nd = 0; nd < 8; nd++) {
                uint32_t bh_[2], bl_[2];
                bh_[0] = *(const uint32_t*)&Vh[(nd * 8 + g) * QP + ko + 2 * t];
                bh_[1] = *(const uint32_t*)&Vh[(nd * 8 + g) * QP + ko + 2 * t + 8];
                bl_[0] = *(const uint32_t*)&Vl[(nd * 8 + g) * QP + ko + 2 * t];
                bl_[1] = *(const uint32_t*)&Vl[(nd * 8 + g) * QP + ko + 2 * t + 8];
                mma16816(oacc[nd], ah, bh_);
                mma16816(oacc[nd], al, bh_);
                mma16816(oacc[nd], ah, bl_);
            }
        }
        __syncthreads();
    }

    const float inv0 = 1.f / (l0 + EPS), inv1 = 1.f / (l1 + EPS);
#pragma unroll
    for (int nd = 0; nd < 8; nd++) {
        const int d = nd * 8 + 2 * t;
        const float vs0 = g_vsum[bh * HD + d];
        const float vs1 = g_vsum[bh * HD + d + 1];
        float o00 = (oacc[nd][0] + EPS_N * vs0) * inv0;
        float o01 = (oacc[nd][1] + EPS_N * vs1) * inv0;
        float o10 = (oacc[nd][2] + EPS_N * vs0) * inv1;
        float o11 = (oacc[nd][3] + EPS_N * vs1) * inv1;
        uint32_t hp, lp;
        size_t o = ((size_t)b * N + qr0) * C + h * HD + d;
        split2(o00, o01, hp, lp);
        *(uint32_t*)(g_chi + o) = hp; *(uint32_t*)(g_clo + o) = lp;
        o = ((size_t)b * N + qr1) * C + h * HD + d;
        split2(o10, o11, hp, lp);
        *(uint32_t*)(g_chi + o) = hp; *(uint32_t*)(g_clo + o) = lp;
    }
}

// ---------------------------------------------------------------------------
// proj GEMM; epilogue adds bias, writes fp32 out. 2 CTAs/SM.
// ---------------------------------------------------------------------------
__global__ __launch_bounds__(256, 2) void proj_tc(const float* __restrict__ bias,
                                                  float* __restrict__ out) {
    extern __shared__ char sm[];
    const int tid = threadIdx.x, wid = tid >> 5, lane = tid & 31;
    const int g = lane >> 2, t = lane & 3;
    const int tile_n = blockIdx.x * CTA_N;
    const int tile_m = blockIdx.y * CTA_M;

    float acc[2][8][4] = {};
    gemm_mainloop(sm,
                  g_chi  + (size_t)tile_m * C, g_clo  + (size_t)tile_m * C,
                  g_wphi + (size_t)tile_n * C, g_wplo + (size_t)tile_n * C,
                  acc);

    const int wm = (wid & 3) * 32, wn = (wid >> 2) * 64;
#pragma unroll
    for (int mt = 0; mt < 2; mt++) {
        const int r0 = tile_m + wm + mt * 16 + g;
#pragma unroll
        for (int nt = 0; nt < 8; nt++) {
            const int col = tile_n + wn + nt * 8 + 2 * t;
            const float b0 = bias[col], b1 = bias[col + 1];
#pragma unroll
            for (int half = 0; half < 2; half++) {
                const int row = r0 + half * 8;
                float* o = out + (size_t)row * C + col;
                *(float2*)o = make_float2(acc[mt][nt][half * 2] + b0,
                                          acc[mt][nt][half * 2 + 1] + b1);
            }
        }
    }
}

// ---------------------------------------------------------------------------
// Launch
// ---------------------------------------------------------------------------
extern "C" void kernel_launch(void* const* d_in, const int* in_sizes, int n_in,
                              void* d_out, int out_size) {
    const float* x = nullptr;
    const float* policy = nullptr;
    const float* w_qkv = nullptr;
    const float* w_proj = nullptr;
    const float* b_proj = nullptr;
    for (int i = 0; i < n_in; i++) {
        switch (in_sizes[i]) {
            case B * N * C:   x      = (const float*)d_in[i]; break;
            case B * N:       policy = (const float*)d_in[i]; break;
            case 3 * C * C:   w_qkv  = (const float*)d_in[i]; break;
            case C * C:       w_proj = (const float*)d_in[i]; break;
            case C:           b_proj = (const float*)d_in[i]; break;
            default: break;
        }
    }
    float* out = (float*)d_out;

    cudaFuncSetAttribute(qkv_tc,  cudaFuncAttributeMaxDynamicSharedMemorySize, SMEM_GEMM);
    cudaFuncSetAttribute(proj_tc, cudaFuncAttributeMaxDynamicSharedMemorySize, SMEM_GEMM);
    cudaFuncSetAttribute(attn_tc, cudaFuncAttributeMaxDynamicSharedMemorySize, SMEM_ATTN);

    convert_hilo<<<(M * C / 4 + 255) / 256, 256>>>(x, 0, M * C);
    convert_hilo<<<(QKVC * C / 4 + 255) / 256, 256>>>(w_qkv, 1, QKVC * C);
    convert_hilo<<<(C * C / 4 + 255) / 256, 256>>>(w_proj, 2, C * C);

    qkv_tc<<<dim3(QKVC / CTA_N, M / CTA_M), 256, SMEM_GEMM>>>();
    vsum_kernel<<<dim3(B * H), 256>>>();
    attn_tc<<<dim3(N / BQ, B * H), 256, SMEM_ATTN>>>(policy);
    proj_tc<<<dim3(C / CTA_N, M / CTA_M), 256, SMEM_GEMM>>>(b_proj, out);
}

// round 9
// speedup vs baseline: 3.0113x; 1.0803x over previous
#include <cuda_runtime.h>
#include <cuda_bf16.h>
#include <cstdint>

// ---------------------------------------------------------------------------
// Problem constants
// ---------------------------------------------------------------------------
namespace {
constexpr int B  = 8;
constexpr int N  = 1024;
constexpr int C  = 768;
constexpr int H  = 12;
constexpr int HD = 64;
constexpr int M  = B * N;          // 8192
constexpr int QKVC = 3 * C;        // 2304
constexpr float SCALE = 0.125f;
constexpr float EPS   = 1e-6f;
constexpr float EPS_N = EPS / (float)N;

// HMMA GEMM tiling (mma.sync m16n8k16 bf16), 128x128 CTA tile, 2 CTAs/SM
constexpr int CTA_M = 128;
constexpr int CTA_N = 128;
constexpr int KC    = 32;
constexpr int KP    = 40;          // padded row elems (80 B, LDSM conflict-free)
constexpr int NCH   = C / KC;      // 24

constexpr int A_BYTES = CTA_M * KP * 2;            // 10240
constexpr int B_BYTES = CTA_N * KP * 2;            // 10240
constexpr int STAGE   = 2 * A_BYTES + 2 * B_BYTES; // 40960
constexpr int SMEM_GEMM = 2 * STAGE;               // 81920 -> 2 CTAs/SM

// Attention tiling
constexpr int BQ = 128;
constexpr int BK = 64;
constexpr int NKC = N / BK;        // 16
constexpr int QP = 72;             // padded row elems (144 B, LDSM conflict-free)
constexpr int AT_TILE  = 64 * QP * 2;              // 9216
constexpr int AT_QHI   = 0;
constexpr int AT_QLO   = 2 * AT_TILE;
constexpr int AT_ST0   = 4 * AT_TILE;
constexpr int AT_SSTR  = 4 * AT_TILE;              // Khi,Klo,Vhi,Vlo
constexpr int AT_POL   = AT_ST0 + 2 * AT_SSTR;
constexpr int SMEM_ATTN = AT_POL + N * 4;          // 114688
}

// ---------------------------------------------------------------------------
// Scratch (device globals; no allocation allowed)
// ---------------------------------------------------------------------------
__device__ float g_vsum[B * H * HD];
__device__ __nv_bfloat16 g_xhi[M * C],     g_xlo[M * C];
__device__ __nv_bfloat16 g_wqhi[QKVC * C], g_wqlo[QKVC * C];
__device__ __nv_bfloat16 g_wphi[C * C],    g_wplo[C * C];
__device__ __nv_bfloat16 g_chi[M * C],     g_clo[M * C];
__device__ __nv_bfloat16 g_qhi[B * H * N * HD], g_qlo[B * H * N * HD]; // [bh][n][d], pre-scaled
__device__ __nv_bfloat16 g_khi[B * H * N * HD], g_klo[B * H * N * HD]; // [bh][n][d]
__device__ __nv_bfloat16 g_vhi[B * H * N * HD], g_vlo[B * H * N * HD]; // [bh][n][d]

// ---------------------------------------------------------------------------
// Helpers
// ---------------------------------------------------------------------------
__device__ __forceinline__ uint32_t smem_u32_of(const void* p) {
    uint32_t a;
    asm("{ .reg .u64 t; cvta.to.shared.u64 t, %1; cvt.u32.u64 %0, t; }"
        : "=r"(a) : "l"(p));
    return a;
}
__device__ __forceinline__ void cp16(uint32_t dst, const void* src) {
    asm volatile("cp.async.cg.shared.global [%0], [%1], 16;"
                 :: "r"(dst), "l"(src));
}
__device__ __forceinline__ void cp_commit() {
    asm volatile("cp.async.commit_group;");
}
template <int NN>
__device__ __forceinline__ void cp_wait() {
    asm volatile("cp.async.wait_group %0;" :: "n"(NN));
}
__device__ __forceinline__ void mma16816(float* d, const uint32_t* a,
                                         const uint32_t* b) {
    asm volatile(
        "mma.sync.aligned.m16n8k16.row.col.f32.bf16.bf16.f32 "
        "{%0,%1,%2,%3}, {%4,%5,%6,%7}, {%8,%9}, {%0,%1,%2,%3};"
        : "+f"(d[0]), "+f"(d[1]), "+f"(d[2]), "+f"(d[3])
        : "r"(a[0]), "r"(a[1]), "r"(a[2]), "r"(a[3]), "r"(b[0]), "r"(b[1]));
}
__device__ __forceinline__ void ldsm4(uint32_t* r, uint32_t a) {
    asm volatile("ldmatrix.sync.aligned.m8n8.x4.shared.b16 {%0,%1,%2,%3}, [%4];"
        : "=r"(r[0]), "=r"(r[1]), "=r"(r[2]), "=r"(r[3]) : "r"(a));
}
__device__ __forceinline__ void ldsm4t(uint32_t* r, uint32_t a) {
    asm volatile("ldmatrix.sync.aligned.m8n8.x4.trans.shared.b16 {%0,%1,%2,%3}, [%4];"
        : "=r"(r[0]), "=r"(r[1]), "=r"(r[2]), "=r"(r[3]) : "r"(a));
}
__device__ __forceinline__ uint32_t pack_bf16x2(float lo, float hi) {
    uint32_t d;
    asm("cvt.rn.bf16x2.f32 %0, %1, %2;" : "=r"(d) : "f"(hi), "f"(lo));
    return d;
}
__device__ __forceinline__ void split2(float v0, float v1,
                                       uint32_t& hi, uint32_t& lo) {
    hi = pack_bf16x2(v0, v1);
    float h0 = __uint_as_float(hi << 16);
    float h1 = __uint_as_float(hi & 0xffff0000u);
    lo = pack_bf16x2(v0 - h0, v1 - h1);
}

// ---------------------------------------------------------------------------
// fp32 -> (bf16 hi, lo) split conversion
// ---------------------------------------------------------------------------
__global__ __launch_bounds__(256) void convert_hilo(const float* __restrict__ src,
                                                    int which, int n) {
    __nv_bfloat16 *hi, *lo;
    if (which == 0)      { hi = g_xhi;  lo = g_xlo;  }
    else if (which == 1) { hi = g_wqhi; lo = g_wqlo; }
    else                 { hi = g_wphi; lo = g_wplo; }
    int i = (blockIdx.x * blockDim.x + threadIdx.x) * 4;
    if (i >= n) return;
    float4 v = *(const float4*)(src + i);
    uint32_t h01, l01, h23, l23;
    split2(v.x, v.y, h01, l01);
    split2(v.z, v.w, h23, l23);
    *(uint32_t*)(hi + i)     = h01;
    *(uint32_t*)(hi + i + 2) = h23;
    *(uint32_t*)(lo + i)     = l01;
    *(uint32_t*)(lo + i + 2) = l23;
}

// ---------------------------------------------------------------------------
// HMMA mainloop (128x128 tile, warp tile 32x64, ldmatrix fragment loads)
// ---------------------------------------------------------------------------
__device__ __forceinline__ void gemm_mainloop(
    char* sm,
    const __nv_bfloat16* __restrict__ a_hi, const __nv_bfloat16* __restrict__ a_lo,
    const __nv_bfloat16* __restrict__ b_hi, const __nv_bfloat16* __restrict__ b_lo,
    float acc[2][8][4])
{
    const int tid  = threadIdx.x;
    const int wid  = tid >> 5, lane = tid & 31;
    const int sel  = lane >> 3, rw = lane & 7;
    const int wm   = (wid & 3) * 32;
    const int wn   = (wid >> 2) * 64;

    const uint32_t su = smem_u32_of(sm);

    // per-thread ldmatrix byte offsets within a tile
    const uint32_t aoff0 = ((wm + (sel & 1) * 8 + rw) * KP + (sel >> 1) * 8) * 2;
    const uint32_t aoff1 = aoff0 + 16 * KP * 2;
    uint32_t boff[4];
#pragma unroll
    for (int ntp = 0; ntp < 4; ntp++)
        boff[ntp] = ((wn + ntp * 16 + (sel >> 1) * 8 + rw) * KP + (sel & 1) * 8) * 2;

    auto fill = [&](int stage, int kc) {
        const uint32_t sb = su + stage * STAGE;
        const int k0 = kc * KC;
#pragma unroll
        for (int i = 0; i < 2; i++) {
            int idx = tid + i * 256;
            int row = idx >> 2, seg = idx & 3;
            uint32_t d = sb + (row * KP + seg * 8) * 2;
            cp16(d, a_hi + (size_t)row * C + k0 + seg * 8);
            cp16(d + A_BYTES, a_lo + (size_t)row * C + k0 + seg * 8);
            uint32_t db = sb + 2 * A_BYTES + (row * KP + seg * 8) * 2;
            cp16(db, b_hi + (size_t)row * C + k0 + seg * 8);
            cp16(db + B_BYTES, b_lo + (size_t)row * C + k0 + seg * 8);
        }
        cp_commit();
    };

    fill(0, 0);

    for (int kc = 0; kc < NCH; kc++) {
        if (kc + 1 < NCH) { fill((kc + 1) & 1, kc + 1); cp_wait<1>(); }
        else              { cp_wait<0>(); }
        __syncthreads();

        const uint32_t sb = su + (kc & 1) * STAGE;
#pragma unroll
        for (int ks = 0; ks < KC / 16; ks++) {
            const uint32_t kb = ks * 32;   // 16 elems * 2 bytes
            uint32_t ah0[4], ah1[4], al0[4], al1[4];
            ldsm4(ah0, sb + aoff0 + kb);
            ldsm4(ah1, sb + aoff1 + kb);
            ldsm4(al0, sb + A_BYTES + aoff0 + kb);
            ldsm4(al1, sb + A_BYTES + aoff1 + kb);
#pragma unroll
            for (int ntp = 0; ntp < 4; ntp++) {
                uint32_t bhp[4], blp[4];
                ldsm4(bhp, sb + 2 * A_BYTES + boff[ntp] + kb);
                ldsm4(blp, sb + 2 * A_BYTES + B_BYTES + boff[ntp] + kb);
#pragma unroll
                for (int j = 0; j < 2; j++) {
                    const int nt = ntp * 2 + j;
                    uint32_t bh_[2] = {bhp[2 * j], bhp[2 * j + 1]};
                    uint32_t bl_[2] = {blp[2 * j], blp[2 * j + 1]};
                    mma16816(acc[0][nt], ah0, bh_);
                    mma16816(acc[0][nt], ah0, bl_);
                    mma16816(acc[0][nt], al0, bh_);
                    mma16816(acc[1][nt], ah1, bh_);
                    mma16816(acc[1][nt], ah1, bl_);
                    mma16816(acc[1][nt], al1, bh_);
                }
            }
        }
        __syncthreads();
    }
}

// ---------------------------------------------------------------------------
// QKV GEMM; epilogue writes q (scaled) / k / v hi-lo [bh][n][d].
// Grid (QKVC/128, M/128), 256 threads, 2 CTAs/SM.
// ---------------------------------------------------------------------------
__global__ __launch_bounds__(256, 2) void qkv_tc() {
    extern __shared__ char sm[];
    const int tid = threadIdx.x, wid = tid >> 5, lane = tid & 31;
    const int g = lane >> 2, t = lane & 3;
    const int tile_n = blockIdx.x * CTA_N;
    const int tile_m = blockIdx.y * CTA_M;

    float acc[2][8][4] = {};
    gemm_mainloop(sm,
                  g_xhi  + (size_t)tile_m * C, g_xlo  + (size_t)tile_m * C,
                  g_wqhi + (size_t)tile_n * C, g_wqlo + (size_t)tile_n * C,
                  acc);

    const int s_ = tile_n / C;                 // 0:q 1:k 2:v
    const int hbase = (tile_n - s_ * C) >> 6;
    __nv_bfloat16* dhi = (s_ == 0) ? g_qhi : (s_ == 1) ? g_khi : g_vhi;
    __nv_bfloat16* dlo = (s_ == 0) ? g_qlo : (s_ == 1) ? g_klo : g_vlo;
    const float sc = (s_ == 0) ? SCALE : 1.0f;
    const int wm = (wid & 3) * 32, wn = (wid >> 2) * 64;

#pragma unroll
    for (int mt = 0; mt < 2; mt++) {
        const int r0 = tile_m + wm + mt * 16 + g;
#pragma unroll
        for (int nt = 0; nt < 8; nt++) {
            const int col = wn + nt * 8 + 2 * t;
            const int h   = hbase + (col >> 6);
            const int d   = col & 63;
#pragma unroll
            for (int half = 0; half < 2; half++) {
                const int row = r0 + half * 8;
                const int bb = row >> 10, nn = row & 1023;
                const int bh = bb * H + h;
                float v0 = acc[mt][nt][half * 2]     * sc;
                float v1 = acc[mt][nt][half * 2 + 1] * sc;
                uint32_t hp, lp;
                split2(v0, v1, hp, lp);
                size_t o = ((size_t)bh * N + nn) * HD + d;
                *(uint32_t*)(dhi + o) = hp;
                *(uint32_t*)(dlo + o) = lp;
            }
        }
    }
}

// ---------------------------------------------------------------------------
// per-(b,h) V row-sum from hi/lo V [bh][n][d]
// ---------------------------------------------------------------------------
__global__ __launch_bounds__(256) void vsum_kernel() {
    __shared__ float red[256];
    const int bh   = blockIdx.x;
    const int d    = threadIdx.x & 63;
    const int part = threadIdx.x >> 6;
    const __nv_bfloat16* ph = g_vhi + (size_t)bh * N * HD + d;
    const __nv_bfloat16* pl = g_vlo + (size_t)bh * N * HD + d;
    float s = 0.f;
#pragma unroll 8
    for (int n = part; n < N; n += 4)
        s += __bfloat162float(ph[(size_t)n * HD]) + __bfloat162float(pl[(size_t)n * HD]);
    red[threadIdx.x] = s;
    __syncthreads();
    if (threadIdx.x < 64)
        g_vsum[bh * HD + threadIdx.x] =
            red[threadIdx.x] + red[64 + threadIdx.x] +
            red[128 + threadIdx.x] + red[192 + threadIdx.x];
}

// ---------------------------------------------------------------------------
// HMMA flash attention; K non-trans ldmatrix, V trans ldmatrix (same layout).
// Grid (N/128, B*H), 256 threads.
// ---------------------------------------------------------------------------
__global__ __launch_bounds__(256, 1) void attn_tc(const float* __restrict__ policy) {
    extern __shared__ char sm[];
    const uint32_t su = smem_u32_of(sm);
    const int tid = threadIdx.x, wid = tid >> 5, lane = tid & 31;
    const int g = lane >> 2, t = lane & 3;
    const int sel = lane >> 3, rw = lane & 7;
    const int bh = blockIdx.y;
    const int b  = bh / H, h = bh - b * H;
    const int n0 = blockIdx.x * BQ;
    const int wm = wid * 16;

    const __nv_bfloat16* qh = g_qhi + (size_t)bh * N * HD;
    const __nv_bfloat16* ql = g_qlo + (size_t)bh * N * HD;
    const __nv_bfloat16* kh = g_khi + (size_t)bh * N * HD;
    const __nv_bfloat16* kl = g_klo + (size_t)bh * N * HD;
    const __nv_bfloat16* vh = g_vhi + (size_t)bh * N * HD;
    const __nv_bfloat16* vl = g_vlo + (size_t)bh * N * HD;

#pragma unroll
    for (int i = 0; i < 4; i++) {
        int idx = tid + i * 256;
        int row = idx >> 3, seg = idx & 7;
        uint32_t d = su + AT_QHI + (row * QP + seg * 8) * 2;
        cp16(d, qh + ((size_t)(n0 + row)) * HD + seg * 8);
        cp16(d + AT_QLO, ql + ((size_t)(n0 + row)) * HD + seg * 8);
    }
    cp16(su + AT_POL + tid * 16, policy + (size_t)b * N + tid * 4);

    auto fillKV = [&](int stage, int kc) {
        const uint32_t sb = su + AT_ST0 + stage * AT_SSTR;
        const int kbase = kc * BK;
#pragma unroll
        for (int i = 0; i < 2; i++) {
            int idx = tid + i * 256;
            int row = idx >> 3, seg = idx & 7;
            uint32_t off = (row * QP + seg * 8) * 2;
            cp16(sb + off,               kh + ((size_t)(kbase + row)) * HD + seg * 8);
            cp16(sb + AT_TILE + off,     kl + ((size_t)(kbase + row)) * HD + seg * 8);
            cp16(sb + 2 * AT_TILE + off, vh + ((size_t)(kbase + row)) * HD + seg * 8);
            cp16(sb + 3 * AT_TILE + off, vl + ((size_t)(kbase + row)) * HD + seg * 8);
        }
        cp_commit();
    };
    fillKV(0, 0);

    const float* pol = (const float*)(sm + AT_POL);

    // ldmatrix per-thread offsets
    const uint32_t qoff = ((wm + (sel & 1) * 8 + rw) * QP + (sel >> 1) * 8) * 2;
    uint32_t koff[4];
#pragma unroll
    for (int ntp = 0; ntp < 4; ntp++)
        koff[ntp] = ((ntp * 16 + (sel >> 1) * 8 + rw) * QP + (sel & 1) * 8) * 2;
    const uint32_t voff = (((sel & 1) * 8 + rw) * QP + (sel >> 1) * 8) * 2;

    float oacc[8][4] = {};
    float m0 = -1e30f, m1 = -1e30f, l0 = 0.f, l1 = 0.f;
    const int qr0 = n0 + wm + g, qr1 = qr0 + 8;

    for (int kc = 0; kc < NKC; kc++) {
        if (kc + 1 < NKC) { fillKV((kc + 1) & 1, kc + 1); cp_wait<1>(); }
        else              { cp_wait<0>(); }
        __syncthreads();

        const uint32_t sb = su + AT_ST0 + (kc & 1) * AT_SSTR;
        const int kbase = kc * BK;

        // ---- S = Q K^T (split 3-product, frags hoisted per k-step) ----
        float s[8][4] = {};
#pragma unroll
        for (int ks = 0; ks < 4; ks++) {
            const uint32_t kb = ks * 32;
            uint32_t qfh[4], qfl[4];
            ldsm4(qfh, su + AT_QHI + qoff + kb);
            ldsm4(qfl, su + AT_QLO + qoff + kb);
#pragma unroll
            for (int ntp = 0; ntp < 4; ntp++) {
                uint32_t khp[4], klp[4];
                ldsm4(khp, sb + koff[ntp] + kb);
                ldsm4(klp, sb + AT_TILE + koff[ntp] + kb);
#pragma unroll
                for (int j = 0; j < 2; j++) {
                    const int nt = ntp * 2 + j;
                    uint32_t bh_[2] = {khp[2 * j], khp[2 * j + 1]};
                    uint32_t bl_[2] = {klp[2 * j], klp[2 * j + 1]};
                    mma16816(s[nt], qfh, bh_);
                    mma16816(s[nt], qfh, bl_);
                    mma16816(s[nt], qfl, bh_);
                }
            }
        }

        // ---- online softmax (max over ALL cols, mask after exp) ----
        float mx0 = -1e30f, mx1 = -1e30f;
#pragma unroll
        for (int nt = 0; nt < 8; nt++) {
            mx0 = fmaxf(mx0, fmaxf(s[nt][0], s[nt][1]));
            mx1 = fmaxf(mx1, fmaxf(s[nt][2], s[nt][3]));
        }
        mx0 = fmaxf(mx0, __shfl_xor_sync(0xffffffffu, mx0, 1));
        mx0 = fmaxf(mx0, __shfl_xor_sync(0xffffffffu, mx0, 2));
        mx1 = fmaxf(mx1, __shfl_xor_sync(0xffffffffu, mx1, 1));
        mx1 = fmaxf(mx1, __shfl_xor_sync(0xffffffffu, mx1, 2));
        const float mn0 = fmaxf(m0, mx0), mn1 = fmaxf(m1, mx1);
        const float a0 = __expf(m0 - mn0), a1 = __expf(m1 - mn1);
        m0 = mn0; m1 = mn1;
        l0 *= a0; l1 *= a1;
#pragma unroll
        for (int nd = 0; nd < 8; nd++) {
            oacc[nd][0] *= a0; oacc[nd][1] *= a0;
            oacc[nd][2] *= a1; oacc[nd][3] *= a1;
        }
        float rs0 = 0.f, rs1 = 0.f;
#pragma unroll
        for (int nt = 0; nt < 8; nt++) {
            const int c0 = kbase + nt * 8 + 2 * t;
            const float ap0 = pol[c0], ap1 = pol[c0 + 1];
            float p00 = __expf(s[nt][0] - m0) * ((c0     == qr0) ? 1.f : ap0);
            float p01 = __expf(s[nt][1] - m0) * ((c0 + 1 == qr0) ? 1.f : ap1);
            float p10 = __expf(s[nt][2] - m1) * ((c0     == qr1) ? 1.f : ap0);
            float p11 = __expf(s[nt][3] - m1) * ((c0 + 1 == qr1) ? 1.f : ap1);
            s[nt][0] = p00; s[nt][1] = p01; s[nt][2] = p10; s[nt][3] = p11;
            rs0 += p00 + p01; rs1 += p10 + p11;
        }
        rs0 += __shfl_xor_sync(0xffffffffu, rs0, 1);
        rs0 += __shfl_xor_sync(0xffffffffu, rs0, 2);
        rs1 += __shfl_xor_sync(0xffffffffu, rs1, 1);
        rs1 += __shfl_xor_sync(0xffffffffu, rs1, 2);
        l0 += rs0; l1 += rs1;

        // ---- O += P V (P in registers; V frags via trans ldmatrix) ----
#pragma unroll
        for (int kk = 0; kk < 4; kk++) {
            uint32_t ah[4], al[4];
            split2(s[2 * kk][0],     s[2 * kk][1],     ah[0], al[0]);
            split2(s[2 * kk][2],     s[2 * kk][3],     ah[1], al[1]);
            split2(s[2 * kk + 1][0], s[2 * kk + 1][1], ah[2], al[2]);
            split2(s[2 * kk + 1][2], s[2 * kk + 1][3], ah[3], al[3]);
            const uint32_t vkb = kk * 16 * QP * 2;
#pragma unroll
            for (int ndp = 0; ndp < 4; ndp++) {
                uint32_t vhp[4], vlp[4];
                const uint32_t vo = voff + vkb + ndp * 32;   // ndp*16 elems
                ldsm4t(vhp, sb + 2 * AT_TILE + vo);
                ldsm4t(vlp, sb + 3 * AT_TILE + vo);
#pragma unroll
                for (int j = 0; j < 2; j++) {
                    const int nd = ndp * 2 + j;
                    uint32_t bh_[2] = {vhp[2 * j], vhp[2 * j + 1]};
                    uint32_t bl_[2] = {vlp[2 * j], vlp[2 * j + 1]};
                    mma16816(oacc[nd], ah, bh_);
                    mma16816(oacc[nd], al, bh_);
                    mma16816(oacc[nd], ah, bl_);
                }
            }
        }
        __syncthreads();
    }

    // ---- epilogue: normalize + eps term, emit ctx hi/lo ----
    const float inv0 = 1.f / (l0 + EPS), inv1 = 1.f / (l1 + EPS);
#pragma unroll
    for (int nd = 0; nd < 8; nd++) {
        const int d = nd * 8 + 2 * t;
        const float vs0 = g_vsum[bh * HD + d];
        const float vs1 = g_vsum[bh * HD + d + 1];
        float o00 = (oacc[nd][0] + EPS_N * vs0) * inv0;
        float o01 = (oacc[nd][1] + EPS_N * vs1) * inv0;
        float o10 = (oacc[nd][2] + EPS_N * vs0) * inv1;
        float o11 = (oacc[nd][3] + EPS_N * vs1) * inv1;
        uint32_t hp, lp;
        size_t o = ((size_t)b * N + qr0) * C + h * HD + d;
        split2(o00, o01, hp, lp);
        *(uint32_t*)(g_chi + o) = hp; *(uint32_t*)(g_clo + o) = lp;
        o = ((size_t)b * N + qr1) * C + h * HD + d;
        split2(o10, o11, hp, lp);
        *(uint32_t*)(g_chi + o) = hp; *(uint32_t*)(g_clo + o) = lp;
    }
}

// ---------------------------------------------------------------------------
// proj GEMM; epilogue adds bias, writes fp32 out. 2 CTAs/SM.
// ---------------------------------------------------------------------------
__global__ __launch_bounds__(256, 2) void proj_tc(const float* __restrict__ bias,
                                                  float* __restrict__ out) {
    extern __shared__ char sm[];
    const int tid = threadIdx.x, wid = tid >> 5, lane = tid & 31;
    const int g = lane >> 2, t = lane & 3;
    const int tile_n = blockIdx.x * CTA_N;
    const int tile_m = blockIdx.y * CTA_M;

    float acc[2][8][4] = {};
    gemm_mainloop(sm,
                  g_chi  + (size_t)tile_m * C, g_clo  + (size_t)tile_m * C,
                  g_wphi + (size_t)tile_n * C, g_wplo + (size_t)tile_n * C,
                  acc);

    const int wm = (wid & 3) * 32, wn = (wid >> 2) * 64;
#pragma unroll
    for (int mt = 0; mt < 2; mt++) {
        const int r0 = tile_m + wm + mt * 16 + g;
#pragma unroll
        for (int nt = 0; nt < 8; nt++) {
            const int col = tile_n + wn + nt * 8 + 2 * t;
            const float b0 = bias[col], b1 = bias[col + 1];
#pragma unroll
            for (int half = 0; half < 2; half++) {
                const int row = r0 + half * 8;
                float* o = out + (size_t)row * C + col;
                *(float2*)o = make_float2(acc[mt][nt][half * 2] + b0,
                                          acc[mt][nt][half * 2 + 1] + b1);
            }
        }
    }
}

// ---------------------------------------------------------------------------
// Launch
// ---------------------------------------------------------------------------
extern "C" void kernel_launch(void* const* d_in, const int* in_sizes, int n_in,
                              void* d_out, int out_size) {
    const float* x = nullptr;
    const float* policy = nullptr;
    const float* w_qkv = nullptr;
    const float* w_proj = nullptr;
    const float* b_proj = nullptr;
    for (int i = 0; i < n_in; i++) {
        switch (in_sizes[i]) {
            case B * N * C:   x      = (const float*)d_in[i]; break;
            case B * N:       policy = (const float*)d_in[i]; break;
            case 3 * C * C:   w_qkv  = (const float*)d_in[i]; break;
            case C * C:       w_proj = (const float*)d_in[i]; break;
            case C:           b_proj = (const float*)d_in[i]; break;
            default: break;
        }
    }
    float* out = (float*)d_out;

    cudaFuncSetAttribute(qkv_tc,  cudaFuncAttributeMaxDynamicSharedMemorySize, SMEM_GEMM);
    cudaFuncSetAttribute(proj_tc, cudaFuncAttributeMaxDynamicSharedMemorySize, SMEM_GEMM);
    cudaFuncSetAttribute(attn_tc, cudaFuncAttributeMaxDynamicSharedMemorySize, SMEM_ATTN);

    convert_hilo<<<(M * C / 4 + 255) / 256, 256>>>(x, 0, M * C);
    convert_hilo<<<(QKVC * C / 4 + 255) / 256, 256>>>(w_qkv, 1, QKVC * C);
    convert_hilo<<<(C * C / 4 + 255) / 256, 256>>>(w_proj, 2, C * C);

    qkv_tc<<<dim3(QKVC / CTA_N, M / CTA_M), 256, SMEM_GEMM>>>();
    vsum_kernel<<<dim3(B * H), 256>>>();
    attn_tc<<<dim3(N / BQ, B * H), 256, SMEM_ATTN>>>(policy);
    proj_tc<<<dim3(C / CTA_N, M / CTA_M), 256, SMEM_GEMM>>>(b_proj, out);
}